// round 4
// baseline (speedup 1.0000x reference)
#include <cuda_runtime.h>
#include <cstdint>

#define Bn   8
#define Nn   32768
#define FDn  32
#define NGn  1024
#define KCHUNK 1024   // kNN smem tile (points) per buffer

// Scratch (no allocations allowed): packed coords + FPS-selected indices
__device__ float4 g_packed[Bn * Nn];     // 4 MB
__device__ int    g_sidx[Bn * NGn];      // global point index of each sample

// Exact (non-FMA, left-to-right) squared distance, matching XLA's
// sum((a-b)**2) elementwise f32 semantics.
__device__ __forceinline__ float d2f(float ax, float ay, float az,
                                     float bx, float by, float bz) {
    float dx = ax - bx, dy = ay - by, dz = az - bz;
    return __fadd_rn(__fadd_rn(__fmul_rn(dx, dx), __fmul_rn(dy, dy)),
                     __fmul_rn(dz, dz));
}

// ---------------------------------------------------------------------------
// small PTX helpers
// ---------------------------------------------------------------------------
__device__ __forceinline__ uint32_t s2u(const void* p) {
    return (uint32_t)__cvta_generic_to_shared(p);
}
__device__ __forceinline__ uint32_t ctarank() {
    uint32_t r; asm("mov.u32 %0, %%cluster_ctarank;" : "=r"(r)); return r;
}
__device__ __forceinline__ uint32_t mapa_u32(uint32_t addr, uint32_t rank) {
    uint32_t r;
    asm("mapa.shared::cluster.u32 %0, %1, %2;" : "=r"(r) : "r"(addr), "r"(rank));
    return r;
}
__device__ __forceinline__ void st_async_u64(uint32_t raddr, unsigned long long v,
                                             uint32_t rmbar) {
    asm volatile("st.async.shared::cluster.mbarrier::complete_tx::bytes.u64 [%0], %1, [%2];"
                 :: "r"(raddr), "l"(v), "r"(rmbar) : "memory");
}
__device__ __forceinline__ void st_async_u32(uint32_t raddr, uint32_t v,
                                             uint32_t rmbar) {
    asm volatile("st.async.shared::cluster.mbarrier::complete_tx::bytes.u32 [%0], %1, [%2];"
                 :: "r"(raddr), "r"(v), "r"(rmbar) : "memory");
}
__device__ __forceinline__ void mbar_init(uint32_t addr, uint32_t cnt) {
    asm volatile("mbarrier.init.shared.b64 [%0], %1;" :: "r"(addr), "r"(cnt) : "memory");
}
__device__ __forceinline__ void mbar_expect_tx(uint32_t addr, uint32_t bytes) {
    asm volatile("mbarrier.arrive.expect_tx.shared.b64 _, [%0], %1;"
                 :: "r"(addr), "r"(bytes) : "memory");
}
__device__ __forceinline__ void mbar_wait_parity(uint32_t addr, uint32_t parity) {
    uint32_t done;
    asm volatile("{\n\t.reg .pred p;\n\t"
                 "mbarrier.try_wait.parity.acquire.cta.shared::cta.b64 p, [%1], %2;\n\t"
                 "selp.b32 %0, 1, 0, p;\n\t}"
                 : "=r"(done) : "r"(addr), "r"(parity) : "memory");
    while (!done) {
        asm volatile("{\n\t.reg .pred p;\n\t"
                     "mbarrier.try_wait.parity.acquire.cta.shared::cta.b64 p, [%1], %2, 0x989680;\n\t"
                     "selp.b32 %0, 1, 0, p;\n\t}"
                     : "=r"(done) : "r"(addr), "r"(parity) : "memory");
    }
}
__device__ __forceinline__ void cluster_sync_asm() {
    asm volatile("barrier.cluster.arrive.aligned;" ::: "memory");
    asm volatile("barrier.cluster.wait.aligned;" ::: "memory");
}
__device__ __forceinline__ void cp_async16(uint32_t saddr, const void* gaddr) {
    asm volatile("cp.async.cg.shared.global [%0], [%1], 16;"
                 :: "r"(saddr), "l"(gaddr) : "memory");
}
__device__ __forceinline__ void cp_commit() {
    asm volatile("cp.async.commit_group;" ::: "memory");
}
template<int N>
__device__ __forceinline__ void cp_wait() {
    asm volatile("cp.async.wait_group %0;" :: "n"(N) : "memory");
}

// ---------------------------------------------------------------------------
// Kernel 1: pack coords [N,3] AoS -> float4 (4 points per thread, f4 loads)
// ---------------------------------------------------------------------------
__global__ void pack_kernel(const float* __restrict__ coord) {
    int t = blockIdx.x * blockDim.x + threadIdx.x;   // handles points 4t..4t+3
    if (t * 4 >= Bn * Nn) return;
    const float4* c4 = (const float4*)(coord + (size_t)t * 12);
    float4 a = c4[0], b = c4[1], c = c4[2];
    g_packed[t * 4 + 0] = make_float4(a.x, a.y, a.z, 0.f);
    g_packed[t * 4 + 1] = make_float4(a.w, b.x, b.y, 0.f);
    g_packed[t * 4 + 2] = make_float4(b.z, b.w, c.x, 0.f);
    g_packed[t * 4 + 3] = make_float4(c.y, c.z, c.w, 0.f);
}

// ---------------------------------------------------------------------------
// FPS (flat exchange): cluster of 16 CTAs x 256 thr x 8 pts/thread per batch.
// Per iteration, each WARP's lanes<16 st.async its warp candidate
// (key = d2bits<<32 | ~local_idx, plus xyz) into slot rank*8+wid of EVERY
// CTA (128 slots). No intra-CTA barrier in the loop: every warp waits the
// mbarrier, picks the global winner from the 128 slots (u64 key max ==
// argmax d2 with smallest-idx tie-break), fetches winner coords by
// slot = idx>>8, updates its register-resident dists.
// Buffer reuse (double buffer) is safe: a warp's phase-k slot reads feed the
// candidate it sends for phase k+1; remote phase-k+2 writes are gated on
// receiving ALL phase-k+1 bytes.
// ---------------------------------------------------------------------------
__global__ void __cluster_dims__(16, 1, 1) __launch_bounds__(256, 1)
fps_kernel16() {
    constexpr int C = 16, T = 256, P = 8;
    constexpr int NW = T / 32;            // 8 warps
    constexpr int PTS = T * P;            // 2048 points per CTA
    constexpr int SLOTS = C * NW;         // 128
    constexpr uint32_t TXB = 20u * SLOTS; // bytes per exchange phase

    __shared__ __align__(16) unsigned long long candKey[2][SLOTS];
    __shared__ __align__(16) unsigned long long candXY[2][SLOTS];
    __shared__ uint32_t candZ[2][SLOTS];
    __shared__ unsigned long long mbarrier_s[2];

    const unsigned FULL = 0xffffffffu;
    int tid = threadIdx.x, lane = tid & 31, wid = tid >> 5;
    uint32_t rank = ctarank();
    int b = blockIdx.x / C;
    uint32_t local_base = rank * PTS + (uint32_t)tid * P;   // idx within batch
    int gbase = b * Nn + (int)local_base;

    uint32_t mb0 = s2u(&mbarrier_s[0]), mb1 = s2u(&mbarrier_s[1]);
    if (tid == 0) { mbar_init(mb0, 1); mbar_init(mb1, 1); }

    // hoisted remote addresses: this warp's slot in CTA 'lane' (lanes < C)
    uint32_t rKey[2], rXY[2], rZ[2], rMB[2];
    if (lane < C) {
        int slot = (int)rank * NW + wid;
#pragma unroll
        for (int q = 0; q < 2; q++) {
            rKey[q] = mapa_u32(s2u(&candKey[q][slot]), (uint32_t)lane);
            rXY[q]  = mapa_u32(s2u(&candXY[q][slot]),  (uint32_t)lane);
            rZ[q]   = mapa_u32(s2u(&candZ[q][slot]),   (uint32_t)lane);
            rMB[q]  = mapa_u32(q ? mb1 : mb0, (uint32_t)lane);
        }
    }

    float px[P], py[P], pz[P], dist[P];
#pragma unroll
    for (int j = 0; j < P; j++) {
        float4 q = g_packed[gbase + j];
        px[j] = q.x; py[j] = q.y; pz[j] = q.z;
    }

    // init: distance to point 0 (state after selecting s0 = 0)
    float4 p0 = g_packed[b * Nn];
    float bd = -1.f; int bj = 0;
#pragma unroll
    for (int j = 0; j < P; j++) {
        float d = d2f(px[j], py[j], pz[j], p0.x, p0.y, p0.z);
        dist[j] = d;
        if (d > bd) { bd = d; bj = j; }   // strict > keeps smallest j (idx)
    }
    if (rank == 0 && tid == 0) g_sidx[b * NGn + 0] = b * Nn;

    __syncthreads();
    cluster_sync_asm();   // all mbarriers initialized before any st.async

    for (int k = 1; k < NGn; k++) {
        int kb = k & 1;
        uint32_t parity = (uint32_t)(((k - 1) >> 1) & 1);
        if (tid == 0) mbar_expect_tx(kb ? mb1 : mb0, TXB);

        // select this lane's best coords (bj in 0..7): 3-level sel tree
        float cx, cy, cz;
        {
            int j = bj;
            float x01 = (j & 1) ? px[1] : px[0], x23 = (j & 1) ? px[3] : px[2];
            float x45 = (j & 1) ? px[5] : px[4], x67 = (j & 1) ? px[7] : px[6];
            float y01 = (j & 1) ? py[1] : py[0], y23 = (j & 1) ? py[3] : py[2];
            float y45 = (j & 1) ? py[5] : py[4], y67 = (j & 1) ? py[7] : py[6];
            float z01 = (j & 1) ? pz[1] : pz[0], z23 = (j & 1) ? pz[3] : pz[2];
            float z45 = (j & 1) ? pz[5] : pz[4], z67 = (j & 1) ? pz[7] : pz[6];
            float xa = (j & 2) ? x23 : x01, xb = (j & 2) ? x67 : x45;
            float ya = (j & 2) ? y23 : y01, yb = (j & 2) ? y67 : y45;
            float za = (j & 2) ? z23 : z01, zb = (j & 2) ? z67 : z45;
            cx = (j & 4) ? xb : xa; cy = (j & 4) ? yb : ya; cz = (j & 4) ? zb : za;
        }
        uint32_t myidx = local_base + (uint32_t)bj;

        // warp argmax (redux + ballot; lane order == idx order)
        uint32_t dbits = __float_as_uint(bd);
        uint32_t wmax  = __reduce_max_sync(FULL, dbits);
        int wsrc = __ffs(__ballot_sync(FULL, dbits == wmax)) - 1;
        uint32_t widx = __shfl_sync(FULL, myidx, wsrc);
        float wx = __shfl_sync(FULL, cx, wsrc);
        float wy = __shfl_sync(FULL, cy, wsrc);
        float wz = __shfl_sync(FULL, cz, wsrc);

        if (lane < C) {
            unsigned long long key =
                ((unsigned long long)wmax << 32) | (0xFFFFFFFFu - widx);
            st_async_u64(rKey[kb], key, rMB[kb]);
            unsigned long long xy =
                ((unsigned long long)__float_as_uint(wy) << 32) | __float_as_uint(wx);
            st_async_u64(rXY[kb], xy, rMB[kb]);
            st_async_u32(rZ[kb], __float_as_uint(wz), rMB[kb]);
        }

        mbar_wait_parity(kb ? mb1 : mb0, parity);

        // pick: each lane max4 over its 4 slots, then split redux (hi, lo)
        const ulonglong2* kp = (const ulonglong2*)&candKey[kb][lane * 4];
        ulonglong2 ka = kp[0], kc = kp[1];
        unsigned long long m01 = (ka.x > ka.y) ? ka.x : ka.y;
        unsigned long long m23 = (kc.x > kc.y) ? kc.x : kc.y;
        unsigned long long lmax = (m01 > m23) ? m01 : m23;
        uint32_t hm = __reduce_max_sync(FULL, (uint32_t)(lmax >> 32));
        uint32_t lo = ((uint32_t)(lmax >> 32) == hm) ? (uint32_t)lmax : 0u;
        uint32_t lm = __reduce_max_sync(FULL, lo);
        uint32_t widx_g = 0xFFFFFFFFu - lm;        // batch-local winner idx
        int slot = (int)(widx_g >> 8);             // rank*8 + warp (contiguous)
        unsigned long long wxy = candXY[kb][slot]; // broadcast LDS
        float gx = __uint_as_float((uint32_t)wxy);
        float gy = __uint_as_float((uint32_t)(wxy >> 32));
        float gz = __uint_as_float(candZ[kb][slot]);
        if (rank == 0 && tid == 0) g_sidx[b * NGn + k] = b * Nn + (int)widx_g;

        // dist update fused with next candidate search
        bd = -1.f; bj = 0;
#pragma unroll
        for (int j = 0; j < P; j++) {
            float nd = d2f(px[j], py[j], pz[j], gx, gy, gz);
            float mn = fminf(dist[j], nd);
            dist[j] = mn;
            if (mn > bd) { bd = mn; bj = j; }
        }
    }
}

// ---------------------------------------------------------------------------
// FPS fallback (proven 2-stage design, cluster 8 x 1024, P=4) — used only if
// non-portable cluster size 16 is rejected.
// ---------------------------------------------------------------------------
__global__ void __cluster_dims__(8, 1, 1) __launch_bounds__(1024, 1)
fps_kernel8() {
    constexpr int C = 8, T = 1024, P = 4;
    constexpr int NW = T / 32;
    constexpr int PTS = T * P;
    constexpr uint32_t TXB = 20u * C;

    __shared__ uint32_t slotD[NW], slotI[NW];
    __shared__ float    slotX[NW], slotY[NW], slotZ[NW];
    __shared__ unsigned long long candDI[2][C];
    __shared__ unsigned long long candXY[2][C];
    __shared__ uint32_t           candZ[2][C];
    __shared__ unsigned long long mbarrier_s[2];

    const unsigned FULL = 0xffffffffu;
    int tid = threadIdx.x, lane = tid & 31, wid = tid >> 5;
    uint32_t rank = ctarank();
    int b = blockIdx.x / C;
    uint32_t local_base = rank * PTS + (uint32_t)tid * P;
    int gbase = b * Nn + (int)local_base;

    uint32_t mb0 = s2u(&mbarrier_s[0]), mb1 = s2u(&mbarrier_s[1]);
    if (tid == 0) { mbar_init(mb0, 1); mbar_init(mb1, 1); }

    uint32_t rDI[2], rXY[2], rZ[2], rMB[2];
    if (wid == 0 && lane < C) {
#pragma unroll
        for (int q = 0; q < 2; q++) {
            rDI[q] = mapa_u32(s2u(&candDI[q][rank]), (uint32_t)lane);
            rXY[q] = mapa_u32(s2u(&candXY[q][rank]), (uint32_t)lane);
            rZ[q]  = mapa_u32(s2u(&candZ[q][rank]),  (uint32_t)lane);
            rMB[q] = mapa_u32(q ? mb1 : mb0, (uint32_t)lane);
        }
    }

    float px[P], py[P], pz[P], dist[P];
#pragma unroll
    for (int j = 0; j < P; j++) {
        float4 q = g_packed[gbase + j];
        px[j] = q.x; py[j] = q.y; pz[j] = q.z;
    }

    float4 p0 = g_packed[b * Nn];
    float bd = -1.f; int bj = 0;
#pragma unroll
    for (int j = 0; j < P; j++) {
        float d = d2f(px[j], py[j], pz[j], p0.x, p0.y, p0.z);
        dist[j] = d;
        if (d > bd) { bd = d; bj = j; }
    }
    if (rank == 0 && tid == 0) g_sidx[b * NGn + 0] = b * Nn;

    __syncthreads();
    cluster_sync_asm();

    for (int k = 1; k < NGn; k++) {
        int kb = k & 1;
        uint32_t parity = (uint32_t)(((k - 1) >> 1) & 1);
        uint32_t mbk = kb ? mb1 : mb0;
        if (tid == 0) mbar_expect_tx(mbk, TXB);

        float cx, cy, cz;
        {
            int j = bj;
            float x01 = (j & 1) ? px[1] : px[0], x23 = (j & 1) ? px[3] : px[2];
            float y01 = (j & 1) ? py[1] : py[0], y23 = (j & 1) ? py[3] : py[2];
            float z01 = (j & 1) ? pz[1] : pz[0], z23 = (j & 1) ? pz[3] : pz[2];
            cx = (j & 2) ? x23 : x01; cy = (j & 2) ? y23 : y01; cz = (j & 2) ? z23 : z01;
        }
        uint32_t myidx = local_base + (uint32_t)bj;

        uint32_t dbits = __float_as_uint(bd);
        uint32_t wmax  = __reduce_max_sync(FULL, dbits);
        int wsrc = __ffs(__ballot_sync(FULL, dbits == wmax)) - 1;
        uint32_t widx = __shfl_sync(FULL, myidx, wsrc);
        float wx = __shfl_sync(FULL, cx, wsrc);
        float wy = __shfl_sync(FULL, cy, wsrc);
        float wz = __shfl_sync(FULL, cz, wsrc);
        if (lane == 0) {
            slotD[wid] = wmax; slotI[wid] = widx;
            slotX[wid] = wx; slotY[wid] = wy; slotZ[wid] = wz;
        }
        __syncthreads();

        if (wid == 0) {
            int sl = lane & (NW - 1);
            uint32_t d = (lane < NW) ? slotD[sl] : 0u;
            uint32_t i = slotI[sl];
            float x = slotX[sl], y = slotY[sl], z = slotZ[sl];
            uint32_t m = __reduce_max_sync(FULL, d);
            int src = __ffs(__ballot_sync(FULL, d == m)) - 1;
            uint32_t ci = __shfl_sync(FULL, i, src);
            float fx = __shfl_sync(FULL, x, src);
            float fy = __shfl_sync(FULL, y, src);
            float fz = __shfl_sync(FULL, z, src);
            if (lane < C) {
                st_async_u64(rDI[kb], ((unsigned long long)m << 32) | ci, rMB[kb]);
                unsigned long long xy =
                    ((unsigned long long)__float_as_uint(fy) << 32) | __float_as_uint(fx);
                st_async_u64(rXY[kb], xy, rMB[kb]);
                st_async_u32(rZ[kb], __float_as_uint(fz), rMB[kb]);
            }
        }

        mbar_wait_parity(mbk, parity);

        int cl = lane & (C - 1);
        unsigned long long di = candDI[kb][cl];
        unsigned long long xy = candXY[kb][cl];
        uint32_t zz = candZ[kb][cl];
        uint32_t d = (lane < C) ? (uint32_t)(di >> 32) : 0u;
        uint32_t m = __reduce_max_sync(FULL, d);
        int src = __ffs(__ballot_sync(FULL, d == m)) - 1;
        uint32_t wl = __shfl_sync(FULL, (uint32_t)di, src);
        unsigned long long wxy = __shfl_sync(FULL, xy, src);
        uint32_t wzb = __shfl_sync(FULL, zz, src);
        float gx = __uint_as_float((uint32_t)wxy);
        float gy = __uint_as_float((uint32_t)(wxy >> 32));
        float gz = __uint_as_float(wzb);
        if (rank == 0 && tid == 0) g_sidx[b * NGn + k] = b * Nn + (int)wl;

        bd = -1.f; bj = 0;
#pragma unroll
        for (int j = 0; j < P; j++) {
            float nd = d2f(px[j], py[j], pz[j], gx, gy, gz);
            float mn = fminf(dist[j], nd);
            dist[j] = mn;
            if (mn > bd) { bd = mn; bj = j; }
        }
    }
}

// ---------------------------------------------------------------------------
// Kernel 3: kNN (top-32 by (d2, idx) lex order) + angle/curvature + outputs.
// 512 threads = 16 warps; one warp per sample; cp.async double-buffered
// 16KB coord tiles shared by the CTA.
// ---------------------------------------------------------------------------
__global__ void __launch_bounds__(512, 1)
knn_kernel(const float* __restrict__ coord, const float* __restrict__ feat,
           const int* __restrict__ labels, float* __restrict__ out) {
    __shared__ float4 sc[2][KCHUNK];
    const unsigned FULL = 0xffffffffu;
    int tid = threadIdx.x, lane = tid & 31, wid = tid >> 5;
    int s = blockIdx.x * 16 + wid;   // sample id [0, 8192)
    int b = s >> 10;                 // batch (1024 samples/batch)
    int si = g_sidx[s];              // global point idx of this sample
    float4 sp = g_packed[si];

    float kd = 3.4028235e38f; unsigned ki = 0xffffffffu;    // kept (per lane)
    float tmd = 3.4028235e38f; unsigned tmi = 0xffffffffu; int tml = 0;

    constexpr int NT = Nn / KCHUNK;  // 32 tiles
    // prologue: stage tile 0
    {
        uint32_t sa = s2u(&sc[0][tid]);
        cp_async16(sa, &g_packed[b * Nn + tid]);
        cp_async16(sa + 512 * 16, &g_packed[b * Nn + tid + 512]);
        cp_commit();
    }
    for (int c = 0; c < NT; c++) {
        int buf = c & 1;
        if (c + 1 < NT) {
            uint32_t sa = s2u(&sc[buf ^ 1][tid]);
            const float4* g = &g_packed[b * Nn + (c + 1) * KCHUNK + tid];
            cp_async16(sa, g);
            cp_async16(sa + 512 * 16, g + 512);
            cp_commit();
            cp_wait<1>();
        } else {
            cp_wait<0>();
        }
        __syncthreads();
        int cb = c * KCHUNK;
        for (int j = 0; j < KCHUNK / 32; j++) {
            float4 q = sc[buf][j * 32 + lane];
            unsigned gi = (unsigned)(b * Nn + cb + j * 32 + lane);
            float d2 = d2f(sp.x, sp.y, sp.z, q.x, q.y, q.z);
            unsigned mask = __ballot_sync(FULL, (d2 < tmd) || (d2 == tmd && gi < tmi));
            while (mask) {
                int ins = __ffs(mask) - 1; mask &= mask - 1;
                float cd = __shfl_sync(FULL, d2, ins);
                unsigned cgi = __shfl_sync(FULL, gi, ins);
                if ((cd < tmd) || (cd == tmd && cgi < tmi)) {   // uniform branch
                    if (lane == tml) { kd = cd; ki = cgi; }
                    unsigned db = __float_as_uint(kd);
                    unsigned m  = __reduce_max_sync(FULL, db);
                    bool tie    = (db == m);
                    unsigned cand = tie ? ki : 0u;
                    unsigned mi2  = __reduce_max_sync(FULL, cand);
                    tml = __ffs(__ballot_sync(FULL, tie && ki == mi2)) - 1;
                    tmd = __uint_as_float(m);
                    tmi = mi2;
                }
            }
        }
        __syncthreads();   // scan done before next overwrite of buf
    }

    // ---- angles: angle = 2*atan2(sqrt(t - a.b), sqrt(t + a.b)), t=|a||b| ----
    float a_own = feat[(size_t)si * FDn + lane];
    float dot = 0.f, an2 = 0.f, bn2 = 0.f;
    const float4* frow = (const float4*)(feat + (size_t)ki * FDn);
#pragma unroll
    for (int g = 0; g < FDn / 4; g++) {
        float4 bv = frow[g];
        float a0 = __shfl_sync(FULL, a_own, g * 4 + 0);
        float a1 = __shfl_sync(FULL, a_own, g * 4 + 1);
        float a2 = __shfl_sync(FULL, a_own, g * 4 + 2);
        float a3 = __shfl_sync(FULL, a_own, g * 4 + 3);
        dot = fmaf(a0, bv.x, dot); an2 = fmaf(a0, a0, an2); bn2 = fmaf(bv.x, bv.x, bn2);
        dot = fmaf(a1, bv.y, dot); an2 = fmaf(a1, a1, an2); bn2 = fmaf(bv.y, bv.y, bn2);
        dot = fmaf(a2, bv.z, dot); an2 = fmaf(a2, a2, an2); bn2 = fmaf(bv.z, bv.z, bn2);
        dot = fmaf(a3, bv.w, dot); an2 = fmaf(a3, a3, an2); bn2 = fmaf(bv.w, bv.w, bn2);
    }
    float t = sqrtf(an2) * sqrtf(bn2);
    float ang = 2.f * atan2f(sqrtf(fmaxf(t - dot, 0.f)), sqrtf(fmaxf(t + dot, 0.f)));
    if (ki == (unsigned)si) ang = 0.f;   // self neighbor contributes 0
    float ssum = ang;
#pragma unroll
    for (int o = 16; o; o >>= 1) ssum += __shfl_xor_sync(FULL, ssum, o);
    float pc = ssum / 31.f;

    // ---- outputs (tuple flattened+concatenated as float32) ----
    const int OFF_FEAT = Bn * NGn * 3;
    const int OFF_SW   = OFF_FEAT + Bn * NGn * (FDn + 1);
    const int OFF_LAB  = OFF_SW + Bn * NGn;
    const int OFF_SIDX = OFF_LAB + Bn * NGn;
    if (lane < 3) out[s * 3 + lane] = coord[si * 3 + lane];
    out[OFF_FEAT + s * 33 + lane] = a_own;
    if (lane == 0) {
        out[OFF_FEAT + s * 33 + 32] = pc;
        out[OFF_SW + s]   = pc > 0.087266f ? 1.f : 0.f;
        out[OFF_LAB + s]  = (float)labels[si];
        out[OFF_SIDX + s] = (float)si;
    }
}

// ---------------------------------------------------------------------------
extern "C" void kernel_launch(void* const* d_in, const int* in_sizes, int n_in,
                              void* d_out, int out_size) {
    const float* coord  = (const float*)d_in[0];
    const float* feat   = (const float*)d_in[1];
    const int*   labels = (const int*)d_in[2];
    float* out = (float*)d_out;

    pack_kernel<<<(Bn * Nn / 4 + 255) / 256, 256>>>(coord);

    cudaError_t rc = cudaFuncSetAttribute(
        (const void*)fps_kernel16,
        cudaFuncAttributeNonPortableClusterSizeAllowed, 1);
    if (rc == cudaSuccess) {
        fps_kernel16<<<Bn * 16, 256>>>();
    } else {
        (void)cudaGetLastError();
        fps_kernel8<<<Bn * 8, 1024>>>();
    }

    knn_kernel<<<(Bn * NGn) / 16, 512>>>(coord, feat, labels, out);
}

// round 5
// speedup vs baseline: 1.4529x; 1.4529x over previous
#include <cuda_runtime.h>
#include <cstdint>

#define Bn   8
#define Nn   32768
#define FDn  32
#define NGn  1024
#define KCHUNK 1024   // kNN smem tile (points) per buffer

// Scratch (no allocations allowed): packed coords + FPS-selected indices
__device__ float4 g_packed[Bn * Nn];     // 4 MB
__device__ int    g_sidx[Bn * NGn];      // global point index of each sample

// Exact (non-FMA, left-to-right) squared distance, matching XLA's
// sum((a-b)**2) elementwise f32 semantics.
__device__ __forceinline__ float d2f(float ax, float ay, float az,
                                     float bx, float by, float bz) {
    float dx = ax - bx, dy = ay - by, dz = az - bz;
    return __fadd_rn(__fadd_rn(__fmul_rn(dx, dx), __fmul_rn(dy, dy)),
                     __fmul_rn(dz, dz));
}

// ---------------------------------------------------------------------------
// small PTX helpers
// ---------------------------------------------------------------------------
__device__ __forceinline__ uint32_t s2u(const void* p) {
    return (uint32_t)__cvta_generic_to_shared(p);
}
__device__ __forceinline__ uint32_t ctarank() {
    uint32_t r; asm("mov.u32 %0, %%cluster_ctarank;" : "=r"(r)); return r;
}
__device__ __forceinline__ uint32_t mapa_u32(uint32_t addr, uint32_t rank) {
    uint32_t r;
    asm("mapa.shared::cluster.u32 %0, %1, %2;" : "=r"(r) : "r"(addr), "r"(rank));
    return r;
}
__device__ __forceinline__ void st_async_u64(uint32_t raddr, unsigned long long v,
                                             uint32_t rmbar) {
    asm volatile("st.async.shared::cluster.mbarrier::complete_tx::bytes.u64 [%0], %1, [%2];"
                 :: "r"(raddr), "l"(v), "r"(rmbar) : "memory");
}
__device__ __forceinline__ void st_async_u32(uint32_t raddr, uint32_t v,
                                             uint32_t rmbar) {
    asm volatile("st.async.shared::cluster.mbarrier::complete_tx::bytes.u32 [%0], %1, [%2];"
                 :: "r"(raddr), "r"(v), "r"(rmbar) : "memory");
}
__device__ __forceinline__ void mbar_init(uint32_t addr, uint32_t cnt) {
    asm volatile("mbarrier.init.shared.b64 [%0], %1;" :: "r"(addr), "r"(cnt) : "memory");
}
__device__ __forceinline__ void mbar_expect_tx(uint32_t addr, uint32_t bytes) {
    asm volatile("mbarrier.arrive.expect_tx.shared.b64 _, [%0], %1;"
                 :: "r"(addr), "r"(bytes) : "memory");
}
__device__ __forceinline__ void mbar_wait_parity(uint32_t addr, uint32_t parity) {
    uint32_t done;
    asm volatile("{\n\t.reg .pred p;\n\t"
                 "mbarrier.try_wait.parity.acquire.cta.shared::cta.b64 p, [%1], %2;\n\t"
                 "selp.b32 %0, 1, 0, p;\n\t}"
                 : "=r"(done) : "r"(addr), "r"(parity) : "memory");
    while (!done) {
        asm volatile("{\n\t.reg .pred p;\n\t"
                     "mbarrier.try_wait.parity.acquire.cta.shared::cta.b64 p, [%1], %2, 0x989680;\n\t"
                     "selp.b32 %0, 1, 0, p;\n\t}"
                     : "=r"(done) : "r"(addr), "r"(parity) : "memory");
    }
}
__device__ __forceinline__ void cluster_sync_asm() {
    asm volatile("barrier.cluster.arrive.aligned;" ::: "memory");
    asm volatile("barrier.cluster.wait.aligned;" ::: "memory");
}
__device__ __forceinline__ void cp_async16(uint32_t saddr, const void* gaddr) {
    asm volatile("cp.async.cg.shared.global [%0], [%1], 16;"
                 :: "r"(saddr), "l"(gaddr) : "memory");
}
__device__ __forceinline__ void cp_commit() {
    asm volatile("cp.async.commit_group;" ::: "memory");
}
template<int N>
__device__ __forceinline__ void cp_wait() {
    asm volatile("cp.async.wait_group %0;" :: "n"(N) : "memory");
}

// ---------------------------------------------------------------------------
// Kernel 1: pack coords [N,3] AoS -> float4 (4 points per thread, f4 loads)
// ---------------------------------------------------------------------------
__global__ void pack_kernel(const float* __restrict__ coord) {
    int t = blockIdx.x * blockDim.x + threadIdx.x;   // handles points 4t..4t+3
    if (t * 4 >= Bn * Nn) return;
    const float4* c4 = (const float4*)(coord + (size_t)t * 12);
    float4 a = c4[0], b = c4[1], c = c4[2];
    g_packed[t * 4 + 0] = make_float4(a.x, a.y, a.z, 0.f);
    g_packed[t * 4 + 1] = make_float4(a.w, b.x, b.y, 0.f);
    g_packed[t * 4 + 2] = make_float4(b.z, b.w, c.x, 0.f);
    g_packed[t * 4 + 3] = make_float4(c.y, c.z, c.w, 0.f);
}

// ---------------------------------------------------------------------------
// FPS: cluster of 16 CTAs x 256 thr x 8 pts/thread per batch (two-stage
// reduce + one all-to-all exchange of ONE candidate per CTA — proven shape).
// Key-only reductions: argmax via redux.max on f32 bits (d2 >= 0) + ballot +
// ffs; lane/slot/rank order == index order at every level, so ffs implements
// jnp.argmax's smallest-index tie-break. Winner coords are looked up ONCE per
// CTA from a 32KB smem tile (broadcast LDS.128) right before the st.async
// exchange — coords never ride the reduction chains.
// ---------------------------------------------------------------------------
__global__ void __cluster_dims__(16, 1, 1) __launch_bounds__(256, 1)
fps_kernel16() {
    constexpr int C = 16, T = 256, P = 8;
    constexpr int NW = T / 32;            // 8 warps
    constexpr int PTS = T * P;            // 2048 points per CTA
    constexpr uint32_t TXB = 20u * C;     // bytes per exchange phase

    __shared__ __align__(16) float4 tile[PTS];          // 32KB coord tile
    __shared__ uint32_t slotD[NW], slotI[NW];
    __shared__ unsigned long long candDI[2][C];
    __shared__ unsigned long long candXY[2][C];
    __shared__ uint32_t           candZ[2][C];
    __shared__ unsigned long long mbarrier_s[2];

    const unsigned FULL = 0xffffffffu;
    int tid = threadIdx.x, lane = tid & 31, wid = tid >> 5;
    uint32_t rank = ctarank();
    int b = blockIdx.x / C;
    uint32_t local_base = rank * PTS + (uint32_t)tid * P;   // idx within batch
    int gbase = b * Nn + (int)local_base;

    uint32_t mb0 = s2u(&mbarrier_s[0]), mb1 = s2u(&mbarrier_s[1]);
    if (tid == 0) { mbar_init(mb0, 1); mbar_init(mb1, 1); }

    // hoisted remote addresses (used only by warp0 lanes < C)
    uint32_t rDI[2], rXY[2], rZ[2], rMB[2];
    if (wid == 0 && lane < C) {
#pragma unroll
        for (int q = 0; q < 2; q++) {
            rDI[q] = mapa_u32(s2u(&candDI[q][rank]), (uint32_t)lane);
            rXY[q] = mapa_u32(s2u(&candXY[q][rank]), (uint32_t)lane);
            rZ[q]  = mapa_u32(s2u(&candZ[q][rank]),  (uint32_t)lane);
            rMB[q] = mapa_u32(q ? mb1 : mb0, (uint32_t)lane);
        }
    }

    float px[P], py[P], pz[P], dist[P];
#pragma unroll
    for (int j = 0; j < P; j++) {
        float4 q = g_packed[gbase + j];
        px[j] = q.x; py[j] = q.y; pz[j] = q.z;
        tile[tid * P + j] = q;                    // CTA-local coord tile
    }

    // init: distance to point 0 (state after selecting s0 = 0)
    float4 p0 = g_packed[b * Nn];
    float bd = -1.f; int bj = 0;
#pragma unroll
    for (int j = 0; j < P; j++) {
        float d = d2f(px[j], py[j], pz[j], p0.x, p0.y, p0.z);
        dist[j] = d;
        if (d > bd) { bd = d; bj = j; }   // strict > keeps smallest j (idx)
    }
    if (rank == 0 && tid == 0) g_sidx[b * NGn + 0] = b * Nn;

    __syncthreads();
    cluster_sync_asm();   // mbarriers + tiles ready before any st.async

    for (int k = 1; k < NGn; k++) {
        int kb = k & 1;
        uint32_t parity = (uint32_t)(((k - 1) >> 1) & 1);
        uint32_t mbk = kb ? mb1 : mb0;
        if (tid == 0) mbar_expect_tx(mbk, TXB);

        // warp argmax: key only (redux + ballot; lane order == idx order)
        uint32_t myidx = local_base + (uint32_t)bj;
        uint32_t dbits = __float_as_uint(bd);
        uint32_t wmax  = __reduce_max_sync(FULL, dbits);
        int wsrc = __ffs(__ballot_sync(FULL, dbits == wmax)) - 1;
        uint32_t widx = __shfl_sync(FULL, myidx, wsrc);
        if (lane == 0) { slotD[wid] = wmax; slotI[wid] = widx; }
        __syncthreads();

        if (wid == 0) {
            int sl = lane & (NW - 1);
            uint32_t d = (lane < NW) ? slotD[sl] : 0u;
            uint32_t i = slotI[sl];
            uint32_t m = __reduce_max_sync(FULL, d);
            int src = __ffs(__ballot_sync(FULL, d == m)) - 1;
            uint32_t ci = __shfl_sync(FULL, i, src);
            float4 w = tile[ci & (PTS - 1)];      // broadcast LDS.128
            if (lane < C) {
                st_async_u64(rDI[kb], ((unsigned long long)m << 32) | ci, rMB[kb]);
                unsigned long long xy =
                    ((unsigned long long)__float_as_uint(w.y) << 32) | __float_as_uint(w.x);
                st_async_u64(rXY[kb], xy, rMB[kb]);
                st_async_u32(rZ[kb], __float_as_uint(w.z), rMB[kb]);
            }
        }

        mbar_wait_parity(mbk, parity);

        // cluster pick: lane r holds candidate of CTA r (rank order == idx order)
        int cl = lane & (C - 1);
        unsigned long long di = candDI[kb][cl];
        unsigned long long xy = candXY[kb][cl];
        uint32_t zz = candZ[kb][cl];
        uint32_t d = (lane < C) ? (uint32_t)(di >> 32) : 0u;
        uint32_t m = __reduce_max_sync(FULL, d);
        int src = __ffs(__ballot_sync(FULL, d == m)) - 1;
        uint32_t wl = __shfl_sync(FULL, (uint32_t)di, src);
        unsigned long long wxy = __shfl_sync(FULL, xy, src);
        uint32_t wzb = __shfl_sync(FULL, zz, src);
        float gx = __uint_as_float((uint32_t)wxy);
        float gy = __uint_as_float((uint32_t)(wxy >> 32));
        float gz = __uint_as_float(wzb);
        if (rank == 0 && tid == 0) g_sidx[b * NGn + k] = b * Nn + (int)wl;

        // dist update fused with next candidate search
        bd = -1.f; bj = 0;
#pragma unroll
        for (int j = 0; j < P; j++) {
            float nd = d2f(px[j], py[j], pz[j], gx, gy, gz);
            float mn = fminf(dist[j], nd);
            dist[j] = mn;
            if (mn > bd) { bd = mn; bj = j; }
        }
    }
}

// ---------------------------------------------------------------------------
// FPS fallback (cluster 8 x 1024, P=4) — only if cluster size 16 is rejected.
// ---------------------------------------------------------------------------
__global__ void __cluster_dims__(8, 1, 1) __launch_bounds__(1024, 1)
fps_kernel8() {
    constexpr int C = 8, T = 1024, P = 4;
    constexpr int NW = T / 32;
    constexpr int PTS = T * P;
    constexpr uint32_t TXB = 20u * C;

    __shared__ uint32_t slotD[NW], slotI[NW];
    __shared__ float    slotX[NW], slotY[NW], slotZ[NW];
    __shared__ unsigned long long candDI[2][C];
    __shared__ unsigned long long candXY[2][C];
    __shared__ uint32_t           candZ[2][C];
    __shared__ unsigned long long mbarrier_s[2];

    const unsigned FULL = 0xffffffffu;
    int tid = threadIdx.x, lane = tid & 31, wid = tid >> 5;
    uint32_t rank = ctarank();
    int b = blockIdx.x / C;
    uint32_t local_base = rank * PTS + (uint32_t)tid * P;
    int gbase = b * Nn + (int)local_base;

    uint32_t mb0 = s2u(&mbarrier_s[0]), mb1 = s2u(&mbarrier_s[1]);
    if (tid == 0) { mbar_init(mb0, 1); mbar_init(mb1, 1); }

    uint32_t rDI[2], rXY[2], rZ[2], rMB[2];
    if (wid == 0 && lane < C) {
#pragma unroll
        for (int q = 0; q < 2; q++) {
            rDI[q] = mapa_u32(s2u(&candDI[q][rank]), (uint32_t)lane);
            rXY[q] = mapa_u32(s2u(&candXY[q][rank]), (uint32_t)lane);
            rZ[q]  = mapa_u32(s2u(&candZ[q][rank]),  (uint32_t)lane);
            rMB[q] = mapa_u32(q ? mb1 : mb0, (uint32_t)lane);
        }
    }

    float px[P], py[P], pz[P], dist[P];
#pragma unroll
    for (int j = 0; j < P; j++) {
        float4 q = g_packed[gbase + j];
        px[j] = q.x; py[j] = q.y; pz[j] = q.z;
    }

    float4 p0 = g_packed[b * Nn];
    float bd = -1.f; int bj = 0;
#pragma unroll
    for (int j = 0; j < P; j++) {
        float d = d2f(px[j], py[j], pz[j], p0.x, p0.y, p0.z);
        dist[j] = d;
        if (d > bd) { bd = d; bj = j; }
    }
    if (rank == 0 && tid == 0) g_sidx[b * NGn + 0] = b * Nn;

    __syncthreads();
    cluster_sync_asm();

    for (int k = 1; k < NGn; k++) {
        int kb = k & 1;
        uint32_t parity = (uint32_t)(((k - 1) >> 1) & 1);
        uint32_t mbk = kb ? mb1 : mb0;
        if (tid == 0) mbar_expect_tx(mbk, TXB);

        float cx, cy, cz;
        {
            int j = bj;
            float x01 = (j & 1) ? px[1] : px[0], x23 = (j & 1) ? px[3] : px[2];
            float y01 = (j & 1) ? py[1] : py[0], y23 = (j & 1) ? py[3] : py[2];
            float z01 = (j & 1) ? pz[1] : pz[0], z23 = (j & 1) ? pz[3] : pz[2];
            cx = (j & 2) ? x23 : x01; cy = (j & 2) ? y23 : y01; cz = (j & 2) ? z23 : z01;
        }
        uint32_t myidx = local_base + (uint32_t)bj;

        uint32_t dbits = __float_as_uint(bd);
        uint32_t wmax  = __reduce_max_sync(FULL, dbits);
        int wsrc = __ffs(__ballot_sync(FULL, dbits == wmax)) - 1;
        uint32_t widx = __shfl_sync(FULL, myidx, wsrc);
        float wx = __shfl_sync(FULL, cx, wsrc);
        float wy = __shfl_sync(FULL, cy, wsrc);
        float wz = __shfl_sync(FULL, cz, wsrc);
        if (lane == 0) {
            slotD[wid] = wmax; slotI[wid] = widx;
            slotX[wid] = wx; slotY[wid] = wy; slotZ[wid] = wz;
        }
        __syncthreads();

        if (wid == 0) {
            int sl = lane & (NW - 1);
            uint32_t d = (lane < NW) ? slotD[sl] : 0u;
            uint32_t i = slotI[sl];
            float x = slotX[sl], y = slotY[sl], z = slotZ[sl];
            uint32_t m = __reduce_max_sync(FULL, d);
            int src = __ffs(__ballot_sync(FULL, d == m)) - 1;
            uint32_t ci = __shfl_sync(FULL, i, src);
            float fx = __shfl_sync(FULL, x, src);
            float fy = __shfl_sync(FULL, y, src);
            float fz = __shfl_sync(FULL, z, src);
            if (lane < C) {
                st_async_u64(rDI[kb], ((unsigned long long)m << 32) | ci, rMB[kb]);
                unsigned long long xy =
                    ((unsigned long long)__float_as_uint(fy) << 32) | __float_as_uint(fx);
                st_async_u64(rXY[kb], xy, rMB[kb]);
                st_async_u32(rZ[kb], __float_as_uint(fz), rMB[kb]);
            }
        }

        mbar_wait_parity(mbk, parity);

        int cl = lane & (C - 1);
        unsigned long long di = candDI[kb][cl];
        unsigned long long xy = candXY[kb][cl];
        uint32_t zz = candZ[kb][cl];
        uint32_t d = (lane < C) ? (uint32_t)(di >> 32) : 0u;
        uint32_t m = __reduce_max_sync(FULL, d);
        int src = __ffs(__ballot_sync(FULL, d == m)) - 1;
        uint32_t wl = __shfl_sync(FULL, (uint32_t)di, src);
        unsigned long long wxy = __shfl_sync(FULL, xy, src);
        uint32_t wzb = __shfl_sync(FULL, zz, src);
        float gx = __uint_as_float((uint32_t)wxy);
        float gy = __uint_as_float((uint32_t)(wxy >> 32));
        float gz = __uint_as_float(wzb);
        if (rank == 0 && tid == 0) g_sidx[b * NGn + k] = b * Nn + (int)wl;

        bd = -1.f; bj = 0;
#pragma unroll
        for (int j = 0; j < P; j++) {
            float nd = d2f(px[j], py[j], pz[j], gx, gy, gz);
            float mn = fminf(dist[j], nd);
            dist[j] = mn;
            if (mn > bd) { bd = mn; bj = j; }
        }
    }
}

// ---------------------------------------------------------------------------
// Kernel 3: kNN (top-32 by (d2, idx) lex order) + angle/curvature + outputs.
// 512 threads = 16 warps; one warp per sample; cp.async double-buffered
// 16KB coord tiles shared by the CTA.
// ---------------------------------------------------------------------------
__global__ void __launch_bounds__(512, 1)
knn_kernel(const float* __restrict__ coord, const float* __restrict__ feat,
           const int* __restrict__ labels, float* __restrict__ out) {
    __shared__ float4 sc[2][KCHUNK];
    const unsigned FULL = 0xffffffffu;
    int tid = threadIdx.x, lane = tid & 31, wid = tid >> 5;
    int s = blockIdx.x * 16 + wid;   // sample id [0, 8192)
    int b = s >> 10;                 // batch (1024 samples/batch)
    int si = g_sidx[s];              // global point idx of this sample
    float4 sp = g_packed[si];

    float kd = 3.4028235e38f; unsigned ki = 0xffffffffu;    // kept (per lane)
    float tmd = 3.4028235e38f; unsigned tmi = 0xffffffffu; int tml = 0;

    constexpr int NT = Nn / KCHUNK;  // 32 tiles
    // prologue: stage tile 0
    {
        uint32_t sa = s2u(&sc[0][tid]);
        cp_async16(sa, &g_packed[b * Nn + tid]);
        cp_async16(sa + 512 * 16, &g_packed[b * Nn + tid + 512]);
        cp_commit();
    }
    for (int c = 0; c < NT; c++) {
        int buf = c & 1;
        if (c + 1 < NT) {
            uint32_t sa = s2u(&sc[buf ^ 1][tid]);
            const float4* g = &g_packed[b * Nn + (c + 1) * KCHUNK + tid];
            cp_async16(sa, g);
            cp_async16(sa + 512 * 16, g + 512);
            cp_commit();
            cp_wait<1>();
        } else {
            cp_wait<0>();
        }
        __syncthreads();
        int cb = c * KCHUNK;
        for (int j = 0; j < KCHUNK / 32; j++) {
            float4 q = sc[buf][j * 32 + lane];
            unsigned gi = (unsigned)(b * Nn + cb + j * 32 + lane);
            float d2 = d2f(sp.x, sp.y, sp.z, q.x, q.y, q.z);
            unsigned mask = __ballot_sync(FULL, (d2 < tmd) || (d2 == tmd && gi < tmi));
            while (mask) {
                int ins = __ffs(mask) - 1; mask &= mask - 1;
                float cd = __shfl_sync(FULL, d2, ins);
                unsigned cgi = __shfl_sync(FULL, gi, ins);
                if ((cd < tmd) || (cd == tmd && cgi < tmi)) {   // uniform branch
                    if (lane == tml) { kd = cd; ki = cgi; }
                    unsigned db = __float_as_uint(kd);
                    unsigned m  = __reduce_max_sync(FULL, db);
                    bool tie    = (db == m);
                    unsigned cand = tie ? ki : 0u;
                    unsigned mi2  = __reduce_max_sync(FULL, cand);
                    tml = __ffs(__ballot_sync(FULL, tie && ki == mi2)) - 1;
                    tmd = __uint_as_float(m);
                    tmi = mi2;
                }
            }
        }
        __syncthreads();   // scan done before next overwrite of buf
    }

    // ---- angles: angle = 2*atan2(sqrt(t - a.b), sqrt(t + a.b)), t=|a||b| ----
    float a_own = feat[(size_t)si * FDn + lane];
    float dot = 0.f, an2 = 0.f, bn2 = 0.f;
    const float4* frow = (const float4*)(feat + (size_t)ki * FDn);
#pragma unroll
    for (int g = 0; g < FDn / 4; g++) {
        float4 bv = frow[g];
        float a0 = __shfl_sync(FULL, a_own, g * 4 + 0);
        float a1 = __shfl_sync(FULL, a_own, g * 4 + 1);
        float a2 = __shfl_sync(FULL, a_own, g * 4 + 2);
        float a3 = __shfl_sync(FULL, a_own, g * 4 + 3);
        dot = fmaf(a0, bv.x, dot); an2 = fmaf(a0, a0, an2); bn2 = fmaf(bv.x, bv.x, bn2);
        dot = fmaf(a1, bv.y, dot); an2 = fmaf(a1, a1, an2); bn2 = fmaf(bv.y, bv.y, bn2);
        dot = fmaf(a2, bv.z, dot); an2 = fmaf(a2, a2, an2); bn2 = fmaf(bv.z, bv.z, bn2);
        dot = fmaf(a3, bv.w, dot); an2 = fmaf(a3, a3, an2); bn2 = fmaf(bv.w, bv.w, bn2);
    }
    float t = sqrtf(an2) * sqrtf(bn2);
    float ang = 2.f * atan2f(sqrtf(fmaxf(t - dot, 0.f)), sqrtf(fmaxf(t + dot, 0.f)));
    if (ki == (unsigned)si) ang = 0.f;   // self neighbor contributes 0
    float ssum = ang;
#pragma unroll
    for (int o = 16; o; o >>= 1) ssum += __shfl_xor_sync(FULL, ssum, o);
    float pc = ssum / 31.f;

    // ---- outputs (tuple flattened+concatenated as float32) ----
    const int OFF_FEAT = Bn * NGn * 3;
    const int OFF_SW   = OFF_FEAT + Bn * NGn * (FDn + 1);
    const int OFF_LAB  = OFF_SW + Bn * NGn;
    const int OFF_SIDX = OFF_LAB + Bn * NGn;
    if (lane < 3) out[s * 3 + lane] = coord[si * 3 + lane];
    out[OFF_FEAT + s * 33 + lane] = a_own;
    if (lane == 0) {
        out[OFF_FEAT + s * 33 + 32] = pc;
        out[OFF_SW + s]   = pc > 0.087266f ? 1.f : 0.f;
        out[OFF_LAB + s]  = (float)labels[si];
        out[OFF_SIDX + s] = (float)si;
    }
}

// ---------------------------------------------------------------------------
extern "C" void kernel_launch(void* const* d_in, const int* in_sizes, int n_in,
                              void* d_out, int out_size) {
    const float* coord  = (const float*)d_in[0];
    const float* feat   = (const float*)d_in[1];
    const int*   labels = (const int*)d_in[2];
    float* out = (float*)d_out;

    pack_kernel<<<(Bn * Nn / 4 + 255) / 256, 256>>>(coord);

    cudaError_t rc = cudaFuncSetAttribute(
        (const void*)fps_kernel16,
        cudaFuncAttributeNonPortableClusterSizeAllowed, 1);
    if (rc == cudaSuccess) {
        fps_kernel16<<<Bn * 16, 256>>>();
    } else {
        (void)cudaGetLastError();
        fps_kernel8<<<Bn * 8, 1024>>>();
    }

    knn_kernel<<<(Bn * NGn) / 16, 512>>>(coord, feat, labels, out);
}

// round 6
// speedup vs baseline: 1.5316x; 1.0542x over previous
#include <cuda_runtime.h>
#include <cstdint>

#define Bn   8
#define Nn   32768
#define FDn  32
#define NGn  1024
#define KCHUNK 1024   // kNN smem tile (points) per buffer

// Scratch (no allocations allowed): packed coords + FPS-selected indices
__device__ float4 g_packed[Bn * Nn];     // 4 MB
__device__ int    g_sidx[Bn * NGn];      // global point index of each sample

// Exact (non-FMA, left-to-right) squared distance, matching XLA's
// sum((a-b)**2) elementwise f32 semantics.
__device__ __forceinline__ float d2f(float ax, float ay, float az,
                                     float bx, float by, float bz) {
    float dx = ax - bx, dy = ay - by, dz = az - bz;
    return __fadd_rn(__fadd_rn(__fmul_rn(dx, dx), __fmul_rn(dy, dy)),
                     __fmul_rn(dz, dz));
}

// ---------------------------------------------------------------------------
// small PTX helpers
// ---------------------------------------------------------------------------
__device__ __forceinline__ uint32_t s2u(const void* p) {
    return (uint32_t)__cvta_generic_to_shared(p);
}
__device__ __forceinline__ uint32_t ctarank() {
    uint32_t r; asm("mov.u32 %0, %%cluster_ctarank;" : "=r"(r)); return r;
}
__device__ __forceinline__ uint32_t mapa_u32(uint32_t addr, uint32_t rank) {
    uint32_t r;
    asm("mapa.shared::cluster.u32 %0, %1, %2;" : "=r"(r) : "r"(addr), "r"(rank));
    return r;
}
__device__ __forceinline__ void st_async_u64(uint32_t raddr, unsigned long long v,
                                             uint32_t rmbar) {
    asm volatile("st.async.shared::cluster.mbarrier::complete_tx::bytes.u64 [%0], %1, [%2];"
                 :: "r"(raddr), "l"(v), "r"(rmbar) : "memory");
}
__device__ __forceinline__ void st_async_u32(uint32_t raddr, uint32_t v,
                                             uint32_t rmbar) {
    asm volatile("st.async.shared::cluster.mbarrier::complete_tx::bytes.u32 [%0], %1, [%2];"
                 :: "r"(raddr), "r"(v), "r"(rmbar) : "memory");
}
__device__ __forceinline__ void mbar_init(uint32_t addr, uint32_t cnt) {
    asm volatile("mbarrier.init.shared.b64 [%0], %1;" :: "r"(addr), "r"(cnt) : "memory");
}
__device__ __forceinline__ void mbar_expect_tx(uint32_t addr, uint32_t bytes) {
    asm volatile("mbarrier.arrive.expect_tx.shared.b64 _, [%0], %1;"
                 :: "r"(addr), "r"(bytes) : "memory");
}
__device__ __forceinline__ void mbar_wait_parity(uint32_t addr, uint32_t parity) {
    uint32_t done;
    asm volatile("{\n\t.reg .pred p;\n\t"
                 "mbarrier.try_wait.parity.acquire.cta.shared::cta.b64 p, [%1], %2;\n\t"
                 "selp.b32 %0, 1, 0, p;\n\t}"
                 : "=r"(done) : "r"(addr), "r"(parity) : "memory");
    while (!done) {
        asm volatile("{\n\t.reg .pred p;\n\t"
                     "mbarrier.try_wait.parity.acquire.cta.shared::cta.b64 p, [%1], %2, 0x989680;\n\t"
                     "selp.b32 %0, 1, 0, p;\n\t}"
                     : "=r"(done) : "r"(addr), "r"(parity) : "memory");
    }
}
__device__ __forceinline__ void cluster_sync_asm() {
    asm volatile("barrier.cluster.arrive.aligned;" ::: "memory");
    asm volatile("barrier.cluster.wait.aligned;" ::: "memory");
}
__device__ __forceinline__ void cp_async16(uint32_t saddr, const void* gaddr) {
    asm volatile("cp.async.cg.shared.global [%0], [%1], 16;"
                 :: "r"(saddr), "l"(gaddr) : "memory");
}
__device__ __forceinline__ void cp_commit() {
    asm volatile("cp.async.commit_group;" ::: "memory");
}
template<int N>
__device__ __forceinline__ void cp_wait() {
    asm volatile("cp.async.wait_group %0;" :: "n"(N) : "memory");
}
// packed f32x2 (sm_103a): IEEE-rn per lane, bit-exact vs scalar ops
__device__ __forceinline__ unsigned long long addx2(unsigned long long a,
                                                    unsigned long long b) {
    unsigned long long r;
    asm("add.rn.f32x2 %0, %1, %2;" : "=l"(r) : "l"(a), "l"(b));
    return r;
}
__device__ __forceinline__ unsigned long long mulx2(unsigned long long a,
                                                    unsigned long long b) {
    unsigned long long r;
    asm("mul.rn.f32x2 %0, %1, %2;" : "=l"(r) : "l"(a), "l"(b));
    return r;
}
__device__ __forceinline__ unsigned long long packx2(float lo, float hi) {
    unsigned long long r;
    asm("mov.b64 %0, {%1, %2};" : "=l"(r) : "f"(lo), "f"(hi));
    return r;
}
__device__ __forceinline__ void unpackx2(float& lo, float& hi,
                                         unsigned long long v) {
    asm("mov.b64 {%0, %1}, %2;" : "=f"(lo), "=f"(hi) : "l"(v));
}

// ---------------------------------------------------------------------------
// Kernel 1: pack coords [N,3] AoS -> float4 (4 points per thread, f4 loads)
// ---------------------------------------------------------------------------
__global__ void pack_kernel(const float* __restrict__ coord) {
    int t = blockIdx.x * blockDim.x + threadIdx.x;   // handles points 4t..4t+3
    if (t * 4 >= Bn * Nn) return;
    const float4* c4 = (const float4*)(coord + (size_t)t * 12);
    float4 a = c4[0], b = c4[1], c = c4[2];
    g_packed[t * 4 + 0] = make_float4(a.x, a.y, a.z, 0.f);
    g_packed[t * 4 + 1] = make_float4(a.w, b.x, b.y, 0.f);
    g_packed[t * 4 + 2] = make_float4(b.z, b.w, c.x, 0.f);
    g_packed[t * 4 + 3] = make_float4(c.y, c.z, c.w, 0.f);
}

// ---------------------------------------------------------------------------
// FPS: cluster of 16 CTAs x 256 thr x 8 pts/thread per batch. Two-stage
// key-only argmax (redux.max on f32 bits + ballot + ffs == jnp.argmax with
// smallest-index tie-break at every level since lane/slot/rank order ==
// index order). One candidate {d2,idx,x,y,z} per CTA exchanged all-to-all
// via st.async + mbarrier complete_tx. Winner coords come from a 32KB smem
// tile (single broadcast LDS.128) — never ride the reductions.
// Distance update uses packed f32x2 add/mul (bit-exact vs scalar) with the
// winner coords pre-negated; per-point argmax index recovered by a post-scan.
// ---------------------------------------------------------------------------
__global__ void __cluster_dims__(16, 1, 1) __launch_bounds__(256, 1)
fps_kernel16() {
    constexpr int C = 16, T = 256, P = 8;
    constexpr int NW = T / 32;            // 8 warps
    constexpr int PTS = T * P;            // 2048 points per CTA
    constexpr uint32_t TXB = 20u * C;     // bytes per exchange phase

    __shared__ __align__(16) float4 tile[PTS];          // 32KB coord tile
    __shared__ uint32_t slotD[NW], slotI[NW];
    __shared__ __align__(16) float4 cand4[2][C];        // {d2, idx, x, y}
    __shared__ uint32_t candZ[2][C];
    __shared__ unsigned long long mbarrier_s[2];

    const unsigned FULL = 0xffffffffu;
    int tid = threadIdx.x, lane = tid & 31, wid = tid >> 5;
    uint32_t rank = ctarank();
    int b = blockIdx.x / C;
    uint32_t local_base = rank * PTS + (uint32_t)tid * P;   // idx within batch
    int gbase = b * Nn + (int)local_base;

    uint32_t mb0 = s2u(&mbarrier_s[0]), mb1 = s2u(&mbarrier_s[1]);
    if (tid == 0) { mbar_init(mb0, 1); mbar_init(mb1, 1); }

    // hoisted remote addresses (used only by warp0 lanes < C)
    uint32_t rC4[2], rZ[2], rMB[2];
    if (wid == 0 && lane < C) {
#pragma unroll
        for (int q = 0; q < 2; q++) {
            rC4[q] = mapa_u32(s2u(&cand4[q][rank]), (uint32_t)lane);
            rZ[q]  = mapa_u32(s2u(&candZ[q][rank]), (uint32_t)lane);
            rMB[q] = mapa_u32(q ? mb1 : mb0, (uint32_t)lane);
        }
    }

    // load own points; keep packed pair registers + coord tile
    float dist[P];
    unsigned long long pxp[P / 2], pyp[P / 2], pzp[P / 2];
    {
        float px[P], py[P], pz[P];
#pragma unroll
        for (int j = 0; j < P; j++) {
            float4 q = g_packed[gbase + j];
            px[j] = q.x; py[j] = q.y; pz[j] = q.z;
            tile[tid * P + j] = q;
        }
#pragma unroll
        for (int p = 0; p < P / 2; p++) {
            pxp[p] = packx2(px[2 * p], px[2 * p + 1]);
            pyp[p] = packx2(py[2 * p], py[2 * p + 1]);
            pzp[p] = packx2(pz[2 * p], pz[2 * p + 1]);
        }
        // init: distance to point 0 (state after selecting s0 = 0)
        float4 p0 = g_packed[b * Nn];
#pragma unroll
        for (int j = 0; j < P; j++)
            dist[j] = d2f(px[j], py[j], pz[j], p0.x, p0.y, p0.z);
    }
    float bd = dist[0];
#pragma unroll
    for (int j = 1; j < P; j++) bd = fmaxf(bd, dist[j]);
    if (rank == 0 && tid == 0) g_sidx[b * NGn + 0] = b * Nn;

    __syncthreads();
    cluster_sync_asm();   // mbarriers + tiles ready before any st.async

    for (int k = 1; k < NGn; k++) {
        int kb = k & 1;
        uint32_t parity = (uint32_t)(((k - 1) >> 1) & 1);
        uint32_t mbk = kb ? mb1 : mb0;
        if (tid == 0) mbar_expect_tx(mbk, TXB);

        // post-scan: smallest j with dist[j] == bd (jnp.argmax tie-break)
        int bj = P - 1;
#pragma unroll
        for (int j = P - 2; j >= 0; j--) bj = (dist[j] == bd) ? j : bj;
        uint32_t myidx = local_base + (uint32_t)bj;

        // warp argmax: key only (redux + ballot; lane order == idx order)
        uint32_t dbits = __float_as_uint(bd);
        uint32_t wmax  = __reduce_max_sync(FULL, dbits);
        int wsrc = __ffs(__ballot_sync(FULL, dbits == wmax)) - 1;
        uint32_t widx = __shfl_sync(FULL, myidx, wsrc);
        if (lane == 0) { slotD[wid] = wmax; slotI[wid] = widx; }
        __syncthreads();

        if (wid == 0) {
            int sl = lane & (NW - 1);
            uint32_t d = (lane < NW) ? slotD[sl] : 0u;
            uint32_t i = slotI[sl];
            uint32_t m = __reduce_max_sync(FULL, d);
            int src = __ffs(__ballot_sync(FULL, d == m)) - 1;
            uint32_t ci = __shfl_sync(FULL, i, src);
            float4 w = tile[ci & (PTS - 1)];      // broadcast LDS.128
            if (lane < C) {
                unsigned long long m1 =
                    ((unsigned long long)ci << 32) | m;                 // {d2, idx}
                unsigned long long m2 =
                    ((unsigned long long)__float_as_uint(w.y) << 32)
                    | __float_as_uint(w.x);                             // {x, y}
                st_async_u64(rC4[kb], m1, rMB[kb]);
                st_async_u64(rC4[kb] + 8, m2, rMB[kb]);
                st_async_u32(rZ[kb], __float_as_uint(w.z), rMB[kb]);
            }
        }

        mbar_wait_parity(mbk, parity);

        // cluster pick: lane r holds candidate of CTA r via one LDS.128
        int cl = lane & (C - 1);
        float4 cv = cand4[kb][cl];
        uint32_t d = (lane < C) ? __float_as_uint(cv.x) : 0u;
        uint32_t m = __reduce_max_sync(FULL, d);
        int src = __ffs(__ballot_sync(FULL, d == m)) - 1;
        uint32_t wl = __float_as_uint(__shfl_sync(FULL, cv.y, src));
        float gx = __shfl_sync(FULL, cv.z, src);
        float gy = __shfl_sync(FULL, cv.w, src);
        float gz = __uint_as_float(candZ[kb][src]);
        if (rank == 0 && tid == 0) g_sidx[b * NGn + k] = b * Nn + (int)wl;

        // packed-f32x2 dist update (pre-negated winner), max accumulator
        unsigned long long ngx = packx2(-gx, -gx);
        unsigned long long ngy = packx2(-gy, -gy);
        unsigned long long ngz = packx2(-gz, -gz);
        bd = -1.f;
#pragma unroll
        for (int p = 0; p < P / 2; p++) {
            unsigned long long dx = addx2(pxp[p], ngx);
            unsigned long long dy = addx2(pyp[p], ngy);
            unsigned long long dz = addx2(pzp[p], ngz);
            unsigned long long s =
                addx2(addx2(mulx2(dx, dx), mulx2(dy, dy)), mulx2(dz, dz));
            float s0, s1; unpackx2(s0, s1, s);
            float m0 = fminf(dist[2 * p], s0);
            float m1 = fminf(dist[2 * p + 1], s1);
            dist[2 * p] = m0; dist[2 * p + 1] = m1;
            bd = fmaxf(bd, m0); bd = fmaxf(bd, m1);
        }
    }
}

// ---------------------------------------------------------------------------
// FPS fallback (cluster 8 x 1024, P=4) — only if cluster size 16 is rejected.
// ---------------------------------------------------------------------------
__global__ void __cluster_dims__(8, 1, 1) __launch_bounds__(1024, 1)
fps_kernel8() {
    constexpr int C = 8, T = 1024, P = 4;
    constexpr int NW = T / 32;
    constexpr int PTS = T * P;
    constexpr uint32_t TXB = 20u * C;

    __shared__ uint32_t slotD[NW], slotI[NW];
    __shared__ float    slotX[NW], slotY[NW], slotZ[NW];
    __shared__ unsigned long long candDI[2][C];
    __shared__ unsigned long long candXY[2][C];
    __shared__ uint32_t           candZ[2][C];
    __shared__ unsigned long long mbarrier_s[2];

    const unsigned FULL = 0xffffffffu;
    int tid = threadIdx.x, lane = tid & 31, wid = tid >> 5;
    uint32_t rank = ctarank();
    int b = blockIdx.x / C;
    uint32_t local_base = rank * PTS + (uint32_t)tid * P;
    int gbase = b * Nn + (int)local_base;

    uint32_t mb0 = s2u(&mbarrier_s[0]), mb1 = s2u(&mbarrier_s[1]);
    if (tid == 0) { mbar_init(mb0, 1); mbar_init(mb1, 1); }

    uint32_t rDI[2], rXY[2], rZ[2], rMB[2];
    if (wid == 0 && lane < C) {
#pragma unroll
        for (int q = 0; q < 2; q++) {
            rDI[q] = mapa_u32(s2u(&candDI[q][rank]), (uint32_t)lane);
            rXY[q] = mapa_u32(s2u(&candXY[q][rank]), (uint32_t)lane);
            rZ[q]  = mapa_u32(s2u(&candZ[q][rank]),  (uint32_t)lane);
            rMB[q] = mapa_u32(q ? mb1 : mb0, (uint32_t)lane);
        }
    }

    float px[P], py[P], pz[P], dist[P];
#pragma unroll
    for (int j = 0; j < P; j++) {
        float4 q = g_packed[gbase + j];
        px[j] = q.x; py[j] = q.y; pz[j] = q.z;
    }

    float4 p0 = g_packed[b * Nn];
    float bd = -1.f; int bj = 0;
#pragma unroll
    for (int j = 0; j < P; j++) {
        float d = d2f(px[j], py[j], pz[j], p0.x, p0.y, p0.z);
        dist[j] = d;
        if (d > bd) { bd = d; bj = j; }
    }
    if (rank == 0 && tid == 0) g_sidx[b * NGn + 0] = b * Nn;

    __syncthreads();
    cluster_sync_asm();

    for (int k = 1; k < NGn; k++) {
        int kb = k & 1;
        uint32_t parity = (uint32_t)(((k - 1) >> 1) & 1);
        uint32_t mbk = kb ? mb1 : mb0;
        if (tid == 0) mbar_expect_tx(mbk, TXB);

        float cx, cy, cz;
        {
            int j = bj;
            float x01 = (j & 1) ? px[1] : px[0], x23 = (j & 1) ? px[3] : px[2];
            float y01 = (j & 1) ? py[1] : py[0], y23 = (j & 1) ? py[3] : py[2];
            float z01 = (j & 1) ? pz[1] : pz[0], z23 = (j & 1) ? pz[3] : pz[2];
            cx = (j & 2) ? x23 : x01; cy = (j & 2) ? y23 : y01; cz = (j & 2) ? z23 : z01;
        }
        uint32_t myidx = local_base + (uint32_t)bj;

        uint32_t dbits = __float_as_uint(bd);
        uint32_t wmax  = __reduce_max_sync(FULL, dbits);
        int wsrc = __ffs(__ballot_sync(FULL, dbits == wmax)) - 1;
        uint32_t widx = __shfl_sync(FULL, myidx, wsrc);
        float wx = __shfl_sync(FULL, cx, wsrc);
        float wy = __shfl_sync(FULL, cy, wsrc);
        float wz = __shfl_sync(FULL, cz, wsrc);
        if (lane == 0) {
            slotD[wid] = wmax; slotI[wid] = widx;
            slotX[wid] = wx; slotY[wid] = wy; slotZ[wid] = wz;
        }
        __syncthreads();

        if (wid == 0) {
            int sl = lane & (NW - 1);
            uint32_t d = (lane < NW) ? slotD[sl] : 0u;
            uint32_t i = slotI[sl];
            float x = slotX[sl], y = slotY[sl], z = slotZ[sl];
            uint32_t m = __reduce_max_sync(FULL, d);
            int src = __ffs(__ballot_sync(FULL, d == m)) - 1;
            uint32_t ci = __shfl_sync(FULL, i, src);
            float fx = __shfl_sync(FULL, x, src);
            float fy = __shfl_sync(FULL, y, src);
            float fz = __shfl_sync(FULL, z, src);
            if (lane < C) {
                st_async_u64(rDI[kb], ((unsigned long long)m << 32) | ci, rMB[kb]);
                unsigned long long xy =
                    ((unsigned long long)__float_as_uint(fy) << 32) | __float_as_uint(fx);
                st_async_u64(rXY[kb], xy, rMB[kb]);
                st_async_u32(rZ[kb], __float_as_uint(fz), rMB[kb]);
            }
        }

        mbar_wait_parity(mbk, parity);

        int cl = lane & (C - 1);
        unsigned long long di = candDI[kb][cl];
        unsigned long long xy = candXY[kb][cl];
        uint32_t zz = candZ[kb][cl];
        uint32_t d = (lane < C) ? (uint32_t)(di >> 32) : 0u;
        uint32_t m = __reduce_max_sync(FULL, d);
        int src = __ffs(__ballot_sync(FULL, d == m)) - 1;
        uint32_t wl = __shfl_sync(FULL, (uint32_t)di, src);
        unsigned long long wxy = __shfl_sync(FULL, xy, src);
        uint32_t wzb = __shfl_sync(FULL, zz, src);
        float gx = __uint_as_float((uint32_t)wxy);
        float gy = __uint_as_float((uint32_t)(wxy >> 32));
        float gz = __uint_as_float(wzb);
        if (rank == 0 && tid == 0) g_sidx[b * NGn + k] = b * Nn + (int)wl;

        bd = -1.f; bj = 0;
#pragma unroll
        for (int j = 0; j < P; j++) {
            float nd = d2f(px[j], py[j], pz[j], gx, gy, gz);
            float mn = fminf(dist[j], nd);
            dist[j] = mn;
            if (mn > bd) { bd = mn; bj = j; }
        }
    }
}

// ---------------------------------------------------------------------------
// Kernel 3: kNN (top-32 by (d2, idx) lex order) + angle/curvature + outputs.
// 512 threads = 16 warps; one warp per sample; cp.async double-buffered
// 16KB coord tiles shared by the CTA.
// ---------------------------------------------------------------------------
__global__ void __launch_bounds__(512, 1)
knn_kernel(const float* __restrict__ coord, const float* __restrict__ feat,
           const int* __restrict__ labels, float* __restrict__ out) {
    __shared__ float4 sc[2][KCHUNK];
    const unsigned FULL = 0xffffffffu;
    int tid = threadIdx.x, lane = tid & 31, wid = tid >> 5;
    int s = blockIdx.x * 16 + wid;   // sample id [0, 8192)
    int b = s >> 10;                 // batch (1024 samples/batch)
    int si = g_sidx[s];              // global point idx of this sample
    float4 sp = g_packed[si];

    float kd = 3.4028235e38f; unsigned ki = 0xffffffffu;    // kept (per lane)
    float tmd = 3.4028235e38f; unsigned tmi = 0xffffffffu; int tml = 0;

    constexpr int NT = Nn / KCHUNK;  // 32 tiles
    // prologue: stage tile 0
    {
        uint32_t sa = s2u(&sc[0][tid]);
        cp_async16(sa, &g_packed[b * Nn + tid]);
        cp_async16(sa + 512 * 16, &g_packed[b * Nn + tid + 512]);
        cp_commit();
    }
    for (int c = 0; c < NT; c++) {
        int buf = c & 1;
        if (c + 1 < NT) {
            uint32_t sa = s2u(&sc[buf ^ 1][tid]);
            const float4* g = &g_packed[b * Nn + (c + 1) * KCHUNK + tid];
            cp_async16(sa, g);
            cp_async16(sa + 512 * 16, g + 512);
            cp_commit();
            cp_wait<1>();
        } else {
            cp_wait<0>();
        }
        __syncthreads();
        int cb = c * KCHUNK;
        for (int j = 0; j < KCHUNK / 32; j++) {
            float4 q = sc[buf][j * 32 + lane];
            unsigned gi = (unsigned)(b * Nn + cb + j * 32 + lane);
            float d2 = d2f(sp.x, sp.y, sp.z, q.x, q.y, q.z);
            unsigned mask = __ballot_sync(FULL, (d2 < tmd) || (d2 == tmd && gi < tmi));
            while (mask) {
                int ins = __ffs(mask) - 1; mask &= mask - 1;
                float cd = __shfl_sync(FULL, d2, ins);
                unsigned cgi = __shfl_sync(FULL, gi, ins);
                if ((cd < tmd) || (cd == tmd && cgi < tmi)) {   // uniform branch
                    if (lane == tml) { kd = cd; ki = cgi; }
                    unsigned db = __float_as_uint(kd);
                    unsigned m  = __reduce_max_sync(FULL, db);
                    bool tie    = (db == m);
                    unsigned cand = tie ? ki : 0u;
                    unsigned mi2  = __reduce_max_sync(FULL, cand);
                    tml = __ffs(__ballot_sync(FULL, tie && ki == mi2)) - 1;
                    tmd = __uint_as_float(m);
                    tmi = mi2;
                }
            }
        }
        __syncthreads();   // scan done before next overwrite of buf
    }

    // ---- angles: angle = 2*atan2(sqrt(t - a.b), sqrt(t + a.b)), t=|a||b| ----
    float a_own = feat[(size_t)si * FDn + lane];
    float dot = 0.f, an2 = 0.f, bn2 = 0.f;
    const float4* frow = (const float4*)(feat + (size_t)ki * FDn);
#pragma unroll
    for (int g = 0; g < FDn / 4; g++) {
        float4 bv = frow[g];
        float a0 = __shfl_sync(FULL, a_own, g * 4 + 0);
        float a1 = __shfl_sync(FULL, a_own, g * 4 + 1);
        float a2 = __shfl_sync(FULL, a_own, g * 4 + 2);
        float a3 = __shfl_sync(FULL, a_own, g * 4 + 3);
        dot = fmaf(a0, bv.x, dot); an2 = fmaf(a0, a0, an2); bn2 = fmaf(bv.x, bv.x, bn2);
        dot = fmaf(a1, bv.y, dot); an2 = fmaf(a1, a1, an2); bn2 = fmaf(bv.y, bv.y, bn2);
        dot = fmaf(a2, bv.z, dot); an2 = fmaf(a2, a2, an2); bn2 = fmaf(bv.z, bv.z, bn2);
        dot = fmaf(a3, bv.w, dot); an2 = fmaf(a3, a3, an2); bn2 = fmaf(bv.w, bv.w, bn2);
    }
    float t = sqrtf(an2) * sqrtf(bn2);
    float ang = 2.f * atan2f(sqrtf(fmaxf(t - dot, 0.f)), sqrtf(fmaxf(t + dot, 0.f)));
    if (ki == (unsigned)si) ang = 0.f;   // self neighbor contributes 0
    float ssum = ang;
#pragma unroll
    for (int o = 16; o; o >>= 1) ssum += __shfl_xor_sync(FULL, ssum, o);
    float pc = ssum / 31.f;

    // ---- outputs (tuple flattened+concatenated as float32) ----
    const int OFF_FEAT = Bn * NGn * 3;
    const int OFF_SW   = OFF_FEAT + Bn * NGn * (FDn + 1);
    const int OFF_LAB  = OFF_SW + Bn * NGn;
    const int OFF_SIDX = OFF_LAB + Bn * NGn;
    if (lane < 3) out[s * 3 + lane] = coord[si * 3 + lane];
    out[OFF_FEAT + s * 33 + lane] = a_own;
    if (lane == 0) {
        out[OFF_FEAT + s * 33 + 32] = pc;
        out[OFF_SW + s]   = pc > 0.087266f ? 1.f : 0.f;
        out[OFF_LAB + s]  = (float)labels[si];
        out[OFF_SIDX + s] = (float)si;
    }
}

// ---------------------------------------------------------------------------
extern "C" void kernel_launch(void* const* d_in, const int* in_sizes, int n_in,
                              void* d_out, int out_size) {
    const float* coord  = (const float*)d_in[0];
    const float* feat   = (const float*)d_in[1];
    const int*   labels = (const int*)d_in[2];
    float* out = (float*)d_out;

    pack_kernel<<<(Bn * Nn / 4 + 255) / 256, 256>>>(coord);

    cudaError_t rc = cudaFuncSetAttribute(
        (const void*)fps_kernel16,
        cudaFuncAttributeNonPortableClusterSizeAllowed, 1);
    if (rc == cudaSuccess) {
        fps_kernel16<<<Bn * 16, 256>>>();
    } else {
        (void)cudaGetLastError();
        fps_kernel8<<<Bn * 8, 1024>>>();
    }

    knn_kernel<<<(Bn * NGn) / 16, 512>>>(coord, feat, labels, out);
}

// round 7
// speedup vs baseline: 1.9626x; 1.2814x over previous
#include <cuda_runtime.h>
#include <cstdint>

#define Bn   8
#define Nn   32768
#define FDn  32
#define NGn  1024
#define KCHUNK 2048   // kNN tile (points) per buffer

typedef unsigned long long u64;

// Scratch (no allocations allowed)
__device__ float4 g_packed[Bn * Nn];        // 4 MB, {x,y,z,0} per point
__device__ u64    g_px[Bn * Nn / 2];        // pair-SoA: {x[2i], x[2i+1]}
__device__ u64    g_py[Bn * Nn / 2];
__device__ u64    g_pz[Bn * Nn / 2];
__device__ int    g_sidx[Bn * NGn];         // FPS-selected global point idx

// Exact (non-FMA, left-to-right) squared distance == XLA sum((a-b)**2) f32.
__device__ __forceinline__ float d2f(float ax, float ay, float az,
                                     float bx, float by, float bz) {
    float dx = ax - bx, dy = ay - by, dz = az - bz;
    return __fadd_rn(__fadd_rn(__fmul_rn(dx, dx), __fmul_rn(dy, dy)),
                     __fmul_rn(dz, dz));
}

// ---------------------------------------------------------------------------
// small PTX helpers
// ---------------------------------------------------------------------------
__device__ __forceinline__ uint32_t s2u(const void* p) {
    return (uint32_t)__cvta_generic_to_shared(p);
}
__device__ __forceinline__ uint32_t ctarank() {
    uint32_t r; asm("mov.u32 %0, %%cluster_ctarank;" : "=r"(r)); return r;
}
__device__ __forceinline__ uint32_t mapa_u32(uint32_t addr, uint32_t rank) {
    uint32_t r;
    asm("mapa.shared::cluster.u32 %0, %1, %2;" : "=r"(r) : "r"(addr), "r"(rank));
    return r;
}
__device__ __forceinline__ void st_async_u64(uint32_t raddr, u64 v, uint32_t rmbar) {
    asm volatile("st.async.shared::cluster.mbarrier::complete_tx::bytes.u64 [%0], %1, [%2];"
                 :: "r"(raddr), "l"(v), "r"(rmbar) : "memory");
}
__device__ __forceinline__ void st_async_u32(uint32_t raddr, uint32_t v, uint32_t rmbar) {
    asm volatile("st.async.shared::cluster.mbarrier::complete_tx::bytes.u32 [%0], %1, [%2];"
                 :: "r"(raddr), "r"(v), "r"(rmbar) : "memory");
}
__device__ __forceinline__ void mbar_init(uint32_t addr, uint32_t cnt) {
    asm volatile("mbarrier.init.shared.b64 [%0], %1;" :: "r"(addr), "r"(cnt) : "memory");
}
__device__ __forceinline__ void mbar_expect_tx(uint32_t addr, uint32_t bytes) {
    asm volatile("mbarrier.arrive.expect_tx.shared.b64 _, [%0], %1;"
                 :: "r"(addr), "r"(bytes) : "memory");
}
__device__ __forceinline__ void mbar_wait_parity(uint32_t addr, uint32_t parity) {
    uint32_t done;
    asm volatile("{\n\t.reg .pred p;\n\t"
                 "mbarrier.try_wait.parity.acquire.cta.shared::cta.b64 p, [%1], %2;\n\t"
                 "selp.b32 %0, 1, 0, p;\n\t}"
                 : "=r"(done) : "r"(addr), "r"(parity) : "memory");
    while (!done) {
        asm volatile("{\n\t.reg .pred p;\n\t"
                     "mbarrier.try_wait.parity.acquire.cta.shared::cta.b64 p, [%1], %2, 0x989680;\n\t"
                     "selp.b32 %0, 1, 0, p;\n\t}"
                     : "=r"(done) : "r"(addr), "r"(parity) : "memory");
    }
}
__device__ __forceinline__ void cluster_sync_asm() {
    asm volatile("barrier.cluster.arrive.aligned;" ::: "memory");
    asm volatile("barrier.cluster.wait.aligned;" ::: "memory");
}
__device__ __forceinline__ void cp_async16(uint32_t saddr, const void* gaddr) {
    asm volatile("cp.async.cg.shared.global [%0], [%1], 16;"
                 :: "r"(saddr), "l"(gaddr) : "memory");
}
__device__ __forceinline__ void cp_commit() {
    asm volatile("cp.async.commit_group;" ::: "memory");
}
template<int N>
__device__ __forceinline__ void cp_wait() {
    asm volatile("cp.async.wait_group %0;" :: "n"(N) : "memory");
}
// packed f32x2 (sm_103a): IEEE-rn per lane, bit-exact vs scalar ops
__device__ __forceinline__ u64 addx2(u64 a, u64 b) {
    u64 r; asm("add.rn.f32x2 %0, %1, %2;" : "=l"(r) : "l"(a), "l"(b)); return r;
}
__device__ __forceinline__ u64 mulx2(u64 a, u64 b) {
    u64 r; asm("mul.rn.f32x2 %0, %1, %2;" : "=l"(r) : "l"(a), "l"(b)); return r;
}
__device__ __forceinline__ u64 packx2(float lo, float hi) {
    u64 r; asm("mov.b64 %0, {%1, %2};" : "=l"(r) : "f"(lo), "f"(hi)); return r;
}
__device__ __forceinline__ void unpackx2(float& lo, float& hi, u64 v) {
    asm("mov.b64 {%0, %1}, %2;" : "=f"(lo), "=f"(hi) : "l"(v));
}

// ---------------------------------------------------------------------------
// Kernel 1: pack coords [N,3] AoS -> float4 AND pair-SoA u64 arrays
// ---------------------------------------------------------------------------
__global__ void pack_kernel(const float* __restrict__ coord) {
    int t = blockIdx.x * blockDim.x + threadIdx.x;   // points 4t..4t+3
    if (t * 4 >= Bn * Nn) return;
    const float4* c4 = (const float4*)(coord + (size_t)t * 12);
    float4 a = c4[0], b = c4[1], c = c4[2];
    // x: a.x a.w b.z c.y | y: a.y b.x b.w c.z | z: a.z b.y c.x c.w
    g_packed[t * 4 + 0] = make_float4(a.x, a.y, a.z, 0.f);
    g_packed[t * 4 + 1] = make_float4(a.w, b.x, b.y, 0.f);
    g_packed[t * 4 + 2] = make_float4(b.z, b.w, c.x, 0.f);
    g_packed[t * 4 + 3] = make_float4(c.y, c.z, c.w, 0.f);
    g_px[2 * t]     = packx2(a.x, a.w);
    g_px[2 * t + 1] = packx2(b.z, c.y);
    g_py[2 * t]     = packx2(a.y, b.x);
    g_py[2 * t + 1] = packx2(b.w, c.z);
    g_pz[2 * t]     = packx2(a.z, b.y);
    g_pz[2 * t + 1] = packx2(c.x, c.w);
}

// ---------------------------------------------------------------------------
// FPS: cluster of 16 CTAs x 256 thr x 8 pts/thread per batch.
// Both argmax stages: redux.max on d2 bits, then redux.max on complemented
// index among the tied (== jnp.argmax smallest-index tie-break; lane/slot/
// rank order == index order everywhere). Exchange ships {d2,x,y,z} (2 u64
// st.async) to every CTA; the winner INDEX goes to rank 0 only (sole
// consumer, for g_sidx). Coords come from a 32KB smem tile (broadcast
// LDS.128). Distance update: packed f32x2 (bit-exact vs scalar).
// ---------------------------------------------------------------------------
__global__ void __cluster_dims__(16, 1, 1) __launch_bounds__(256, 1)
fps_kernel16() {
    constexpr int C = 16, T = 256, P = 8;
    constexpr int NW = T / 32;            // 8 warps
    constexpr int PTS = T * P;            // 2048 points per CTA

    __shared__ __align__(16) float4 tile[PTS];          // 32KB coord tile
    __shared__ u64 slotK[NW];                            // {d2bits, ~idx}
    __shared__ __align__(16) float4 cand4[2][C];         // {d2, x, y, z}
    __shared__ uint32_t candI[2][C];                     // idx (rank0 only)
    __shared__ u64 mbarrier_s[2];

    const unsigned FULL = 0xffffffffu;
    int tid = threadIdx.x, lane = tid & 31, wid = tid >> 5;
    uint32_t rank = ctarank();
    int b = blockIdx.x / C;
    uint32_t local_base = rank * PTS + (uint32_t)tid * P;
    int gbase = b * Nn + (int)local_base;
    const uint32_t TXB = (rank == 0) ? 20u * C : 16u * C;

    uint32_t mb0 = s2u(&mbarrier_s[0]), mb1 = s2u(&mbarrier_s[1]);
    if (tid == 0) { mbar_init(mb0, 1); mbar_init(mb1, 1); }

    // hoisted remote addresses (warp0 only; rI targets rank 0)
    uint32_t rC4[2], rI[2], rMB[2];
    if (wid == 0 && lane < C) {
#pragma unroll
        for (int q = 0; q < 2; q++) {
            rC4[q] = mapa_u32(s2u(&cand4[q][rank]), (uint32_t)lane);
            rI[q]  = mapa_u32(s2u(&candI[q][rank]), 0u);
            rMB[q] = mapa_u32(q ? mb1 : mb0, (uint32_t)lane);
        }
    }

    float dist[P];
    u64 pxp[P / 2], pyp[P / 2], pzp[P / 2];
    {
        float px[P], py[P], pz[P];
#pragma unroll
        for (int j = 0; j < P; j++) {
            float4 q = g_packed[gbase + j];
            px[j] = q.x; py[j] = q.y; pz[j] = q.z;
            tile[tid * P + j] = q;
        }
#pragma unroll
        for (int p = 0; p < P / 2; p++) {
            pxp[p] = packx2(px[2 * p], px[2 * p + 1]);
            pyp[p] = packx2(py[2 * p], py[2 * p + 1]);
            pzp[p] = packx2(pz[2 * p], pz[2 * p + 1]);
        }
        float4 p0 = g_packed[b * Nn];
#pragma unroll
        for (int j = 0; j < P; j++)
            dist[j] = d2f(px[j], py[j], pz[j], p0.x, p0.y, p0.z);
    }
    float bd = dist[0];
#pragma unroll
    for (int j = 1; j < P; j++) bd = fmaxf(bd, dist[j]);
    if (rank == 0 && tid == 0) g_sidx[b * NGn + 0] = b * Nn;

    __syncthreads();
    cluster_sync_asm();   // mbarriers + tiles ready before any st.async

    for (int k = 1; k < NGn; k++) {
        int kb = k & 1;
        uint32_t parity = (uint32_t)(((k - 1) >> 1) & 1);
        uint32_t mbk = kb ? mb1 : mb0;
        if (tid == 0) mbar_expect_tx(mbk, TXB);

        // smallest j with dist[j] == bd (jnp.argmax tie-break)
        int bj = P - 1;
#pragma unroll
        for (int j = P - 2; j >= 0; j--) bj = (dist[j] == bd) ? j : bj;
        uint32_t myinv = 0xFFFFFFFFu - (local_base + (uint32_t)bj);

        // warp argmax: redux(d2) then redux(~idx among tied)
        uint32_t dbits = __float_as_uint(bd);
        uint32_t wmax  = __reduce_max_sync(FULL, dbits);
        uint32_t inv   = (dbits == wmax) ? myinv : 0u;
        uint32_t winv  = __reduce_max_sync(FULL, inv);
        if (lane == 0) slotK[wid] = ((u64)wmax << 32) | winv;
        __syncthreads();

        if (wid == 0) {
            u64 k0 = slotK[lane & (NW - 1)];
            uint32_t hi = (lane < NW) ? (uint32_t)(k0 >> 32) : 0u;
            uint32_t hm = __reduce_max_sync(FULL, hi);
            uint32_t lo = (hi == hm) ? (uint32_t)k0 : 0u;
            uint32_t lm = __reduce_max_sync(FULL, lo);
            uint32_t ci = 0xFFFFFFFFu - lm;         // batch-local winner idx
            float4 w = tile[ci & (PTS - 1)];        // broadcast LDS.128
            if (lane < C) {
                st_async_u64(rC4[kb],
                             ((u64)__float_as_uint(w.x) << 32) | hm, rMB[kb]);
                st_async_u64(rC4[kb] + 8,
                             ((u64)__float_as_uint(w.z) << 32)
                             | __float_as_uint(w.y), rMB[kb]);
            }
            if (lane == 0) st_async_u32(rI[kb], ci, rMB[kb]);
        }

        mbar_wait_parity(mbk, parity);

        // cluster pick: lane r holds candidate of CTA r (one LDS.128)
        int cl = lane & (C - 1);
        float4 cv = cand4[kb][cl];     // {d2, x, y, z}
        uint32_t d = (lane < C) ? __float_as_uint(cv.x) : 0u;
        uint32_t m = __reduce_max_sync(FULL, d);
        int src = __ffs(__ballot_sync(FULL, d == m)) - 1;  // smallest rank==idx
        float gx = __shfl_sync(FULL, cv.y, src);
        float gy = __shfl_sync(FULL, cv.z, src);
        float gz = __shfl_sync(FULL, cv.w, src);
        if (rank == 0 && tid == 0)
            g_sidx[b * NGn + k] = b * Nn + (int)candI[kb][src];

        // packed-f32x2 dist update (pre-negated winner), max accumulator
        u64 ngx = packx2(-gx, -gx);
        u64 ngy = packx2(-gy, -gy);
        u64 ngz = packx2(-gz, -gz);
        bd = -1.f;
#pragma unroll
        for (int p = 0; p < P / 2; p++) {
            u64 dx = addx2(pxp[p], ngx);
            u64 dy = addx2(pyp[p], ngy);
            u64 dz = addx2(pzp[p], ngz);
            u64 s = addx2(addx2(mulx2(dx, dx), mulx2(dy, dy)), mulx2(dz, dz));
            float s0, s1; unpackx2(s0, s1, s);
            float m0 = fminf(dist[2 * p], s0);
            float m1 = fminf(dist[2 * p + 1], s1);
            dist[2 * p] = m0; dist[2 * p + 1] = m1;
            bd = fmaxf(bd, m0); bd = fmaxf(bd, m1);
        }
    }
}

// ---------------------------------------------------------------------------
// FPS fallback (cluster 8 x 1024, P=4) — only if cluster size 16 is rejected.
// ---------------------------------------------------------------------------
__global__ void __cluster_dims__(8, 1, 1) __launch_bounds__(1024, 1)
fps_kernel8() {
    constexpr int C = 8, T = 1024, P = 4;
    constexpr int NW = T / 32;
    constexpr int PTS = T * P;
    constexpr uint32_t TXB = 20u * C;

    __shared__ uint32_t slotD[NW], slotI[NW];
    __shared__ float    slotX[NW], slotY[NW], slotZ[NW];
    __shared__ u64      candDI[2][C];
    __shared__ u64      candXY[2][C];
    __shared__ uint32_t candZ[2][C];
    __shared__ u64      mbarrier_s[2];

    const unsigned FULL = 0xffffffffu;
    int tid = threadIdx.x, lane = tid & 31, wid = tid >> 5;
    uint32_t rank = ctarank();
    int b = blockIdx.x / C;
    uint32_t local_base = rank * PTS + (uint32_t)tid * P;
    int gbase = b * Nn + (int)local_base;

    uint32_t mb0 = s2u(&mbarrier_s[0]), mb1 = s2u(&mbarrier_s[1]);
    if (tid == 0) { mbar_init(mb0, 1); mbar_init(mb1, 1); }

    uint32_t rDI[2], rXY[2], rZ[2], rMB[2];
    if (wid == 0 && lane < C) {
#pragma unroll
        for (int q = 0; q < 2; q++) {
            rDI[q] = mapa_u32(s2u(&candDI[q][rank]), (uint32_t)lane);
            rXY[q] = mapa_u32(s2u(&candXY[q][rank]), (uint32_t)lane);
            rZ[q]  = mapa_u32(s2u(&candZ[q][rank]),  (uint32_t)lane);
            rMB[q] = mapa_u32(q ? mb1 : mb0, (uint32_t)lane);
        }
    }

    float px[P], py[P], pz[P], dist[P];
#pragma unroll
    for (int j = 0; j < P; j++) {
        float4 q = g_packed[gbase + j];
        px[j] = q.x; py[j] = q.y; pz[j] = q.z;
    }

    float4 p0 = g_packed[b * Nn];
    float bd = -1.f; int bj = 0;
#pragma unroll
    for (int j = 0; j < P; j++) {
        float d = d2f(px[j], py[j], pz[j], p0.x, p0.y, p0.z);
        dist[j] = d;
        if (d > bd) { bd = d; bj = j; }
    }
    if (rank == 0 && tid == 0) g_sidx[b * NGn + 0] = b * Nn;

    __syncthreads();
    cluster_sync_asm();

    for (int k = 1; k < NGn; k++) {
        int kb = k & 1;
        uint32_t parity = (uint32_t)(((k - 1) >> 1) & 1);
        uint32_t mbk = kb ? mb1 : mb0;
        if (tid == 0) mbar_expect_tx(mbk, TXB);

        float cx, cy, cz;
        {
            int j = bj;
            float x01 = (j & 1) ? px[1] : px[0], x23 = (j & 1) ? px[3] : px[2];
            float y01 = (j & 1) ? py[1] : py[0], y23 = (j & 1) ? py[3] : py[2];
            float z01 = (j & 1) ? pz[1] : pz[0], z23 = (j & 1) ? pz[3] : pz[2];
            cx = (j & 2) ? x23 : x01; cy = (j & 2) ? y23 : y01; cz = (j & 2) ? z23 : z01;
        }
        uint32_t myidx = local_base + (uint32_t)bj;

        uint32_t dbits = __float_as_uint(bd);
        uint32_t wmax  = __reduce_max_sync(FULL, dbits);
        int wsrc = __ffs(__ballot_sync(FULL, dbits == wmax)) - 1;
        uint32_t widx = __shfl_sync(FULL, myidx, wsrc);
        float wx = __shfl_sync(FULL, cx, wsrc);
        float wy = __shfl_sync(FULL, cy, wsrc);
        float wz = __shfl_sync(FULL, cz, wsrc);
        if (lane == 0) {
            slotD[wid] = wmax; slotI[wid] = widx;
            slotX[wid] = wx; slotY[wid] = wy; slotZ[wid] = wz;
        }
        __syncthreads();

        if (wid == 0) {
            int sl = lane & (NW - 1);
            uint32_t d = (lane < NW) ? slotD[sl] : 0u;
            uint32_t i = slotI[sl];
            float x = slotX[sl], y = slotY[sl], z = slotZ[sl];
            uint32_t m = __reduce_max_sync(FULL, d);
            int src = __ffs(__ballot_sync(FULL, d == m)) - 1;
            uint32_t ci = __shfl_sync(FULL, i, src);
            float fx = __shfl_sync(FULL, x, src);
            float fy = __shfl_sync(FULL, y, src);
            float fz = __shfl_sync(FULL, z, src);
            if (lane < C) {
                st_async_u64(rDI[kb], ((u64)m << 32) | ci, rMB[kb]);
                st_async_u64(rXY[kb],
                             ((u64)__float_as_uint(fy) << 32) | __float_as_uint(fx),
                             rMB[kb]);
                st_async_u32(rZ[kb], __float_as_uint(fz), rMB[kb]);
            }
        }

        mbar_wait_parity(mbk, parity);

        int cl = lane & (C - 1);
        u64 di = candDI[kb][cl];
        u64 xy = candXY[kb][cl];
        uint32_t zz = candZ[kb][cl];
        uint32_t d = (lane < C) ? (uint32_t)(di >> 32) : 0u;
        uint32_t m = __reduce_max_sync(FULL, d);
        int src = __ffs(__ballot_sync(FULL, d == m)) - 1;
        uint32_t wl = __shfl_sync(FULL, (uint32_t)di, src);
        u64 wxy = __shfl_sync(FULL, xy, src);
        uint32_t wzb = __shfl_sync(FULL, zz, src);
        float gx = __uint_as_float((uint32_t)wxy);
        float gy = __uint_as_float((uint32_t)(wxy >> 32));
        float gz = __uint_as_float(wzb);
        if (rank == 0 && tid == 0) g_sidx[b * NGn + k] = b * Nn + (int)wl;

        bd = -1.f; bj = 0;
#pragma unroll
        for (int j = 0; j < P; j++) {
            float nd = d2f(px[j], py[j], pz[j], gx, gy, gz);
            float mn = fminf(dist[j], nd);
            dist[j] = mn;
            if (mn > bd) { bd = mn; bj = j; }
        }
    }
}

// ---------------------------------------------------------------------------
// Kernel 3: kNN (top-32 by (d2, idx) lex order) + angle/curvature + outputs.
// Pair-SoA scan: 3 LDS.64 + 8 packed-f32x2 ops per 64 points (bit-exact);
// neighbor gi computed from ballot src (no shfl). Kept set is insertion-
// order independent (replace-lex-max). cp.async double-buffered 24KB tiles.
// ---------------------------------------------------------------------------
__global__ void __launch_bounds__(512, 1)
knn_kernel(const float* __restrict__ coord, const float* __restrict__ feat,
           const int* __restrict__ labels, float* __restrict__ out) {
    __shared__ u64 scx[2][KCHUNK / 2];
    __shared__ u64 scy[2][KCHUNK / 2];
    __shared__ u64 scz[2][KCHUNK / 2];
    const unsigned FULL = 0xffffffffu;
    int tid = threadIdx.x, lane = tid & 31, wid = tid >> 5;
    int s = blockIdx.x * 16 + wid;   // sample id [0, 8192)
    int b = s >> 10;                 // batch
    int si = g_sidx[s];
    float4 sp = g_packed[si];
    u64 nspx = packx2(-sp.x, -sp.x);
    u64 nspy = packx2(-sp.y, -sp.y);
    u64 nspz = packx2(-sp.z, -sp.z);

    float kd = 3.4028235e38f; unsigned ki = 0xffffffffu;    // kept (per lane)
    float tmd = 3.4028235e38f; unsigned tmi = 0xffffffffu; int tml = 0;

    constexpr int NT = Nn / KCHUNK;      // 16 tiles
    int pbase = b * (Nn / 2);
    // stage tile c into buffer buf: 1024 pairs x 8B per axis = 3 cp16/thread
    auto stage = [&](int buf, int c) {
        int po = pbase + c * (KCHUNK / 2) + tid * 2;
        cp_async16(s2u(&scx[buf][tid * 2]), &g_px[po]);
        cp_async16(s2u(&scy[buf][tid * 2]), &g_py[po]);
        cp_async16(s2u(&scz[buf][tid * 2]), &g_pz[po]);
        cp_commit();
    };
    stage(0, 0);
    for (int c = 0; c < NT; c++) {
        int buf = c & 1;
        if (c + 1 < NT) { stage(buf ^ 1, c + 1); cp_wait<1>(); }
        else           { cp_wait<0>(); }
        __syncthreads();
        int cbase = b * Nn + c * KCHUNK;
        for (int j = 0; j < KCHUNK / 64; j++) {
            int pi = j * 32 + lane;
            u64 dx = addx2(scx[buf][pi], nspx);
            u64 dy = addx2(scy[buf][pi], nspy);
            u64 dz = addx2(scz[buf][pi], nspz);
            u64 ss = addx2(addx2(mulx2(dx, dx), mulx2(dy, dy)), mulx2(dz, dz));
            float d2A, d2B; unpackx2(d2A, d2B, ss);
            int gb = cbase + j * 64;
            unsigned giA = (unsigned)(gb + 2 * lane);
            unsigned giB = giA + 1;
            unsigned mA = __ballot_sync(FULL, (d2A < tmd) || (d2A == tmd && giA < tmi));
            unsigned mB = __ballot_sync(FULL, (d2B < tmd) || (d2B == tmd && giB < tmi));
            while (mA) {
                int ins = __ffs(mA) - 1; mA &= mA - 1;
                float cd = __shfl_sync(FULL, d2A, ins);
                unsigned cgi = (unsigned)(gb + 2 * ins);
                if ((cd < tmd) || (cd == tmd && cgi < tmi)) {
                    if (lane == tml) { kd = cd; ki = cgi; }
                    unsigned db = __float_as_uint(kd);
                    unsigned m  = __reduce_max_sync(FULL, db);
                    bool tie    = (db == m);
                    unsigned mi2 = __reduce_max_sync(FULL, tie ? ki : 0u);
                    tml = __ffs(__ballot_sync(FULL, tie && ki == mi2)) - 1;
                    tmd = __uint_as_float(m); tmi = mi2;
                }
            }
            while (mB) {
                int ins = __ffs(mB) - 1; mB &= mB - 1;
                float cd = __shfl_sync(FULL, d2B, ins);
                unsigned cgi = (unsigned)(gb + 2 * ins + 1);
                if ((cd < tmd) || (cd == tmd && cgi < tmi)) {
                    if (lane == tml) { kd = cd; ki = cgi; }
                    unsigned db = __float_as_uint(kd);
                    unsigned m  = __reduce_max_sync(FULL, db);
                    bool tie    = (db == m);
                    unsigned mi2 = __reduce_max_sync(FULL, tie ? ki : 0u);
                    tml = __ffs(__ballot_sync(FULL, tie && ki == mi2)) - 1;
                    tmd = __uint_as_float(m); tmi = mi2;
                }
            }
        }
        __syncthreads();   // scan done before next overwrite of buf
    }

    // ---- angles: angle = 2*atan2(sqrt(t - a.b), sqrt(t + a.b)), t=|a||b| ----
    float a_own = feat[(size_t)si * FDn + lane];
    float dot = 0.f, an2 = 0.f, bn2 = 0.f;
    const float4* frow = (const float4*)(feat + (size_t)ki * FDn);
#pragma unroll
    for (int g = 0; g < FDn / 4; g++) {
        float4 bv = frow[g];
        float a0 = __shfl_sync(FULL, a_own, g * 4 + 0);
        float a1 = __shfl_sync(FULL, a_own, g * 4 + 1);
        float a2 = __shfl_sync(FULL, a_own, g * 4 + 2);
        float a3 = __shfl_sync(FULL, a_own, g * 4 + 3);
        dot = fmaf(a0, bv.x, dot); an2 = fmaf(a0, a0, an2); bn2 = fmaf(bv.x, bv.x, bn2);
        dot = fmaf(a1, bv.y, dot); an2 = fmaf(a1, a1, an2); bn2 = fmaf(bv.y, bv.y, bn2);
        dot = fmaf(a2, bv.z, dot); an2 = fmaf(a2, a2, an2); bn2 = fmaf(bv.z, bv.z, bn2);
        dot = fmaf(a3, bv.w, dot); an2 = fmaf(a3, a3, an2); bn2 = fmaf(bv.w, bv.w, bn2);
    }
    float t = sqrtf(an2) * sqrtf(bn2);
    float ang = 2.f * atan2f(sqrtf(fmaxf(t - dot, 0.f)), sqrtf(fmaxf(t + dot, 0.f)));
    if (ki == (unsigned)si) ang = 0.f;   // self neighbor contributes 0
    float ssum = ang;
#pragma unroll
    for (int o = 16; o; o >>= 1) ssum += __shfl_xor_sync(FULL, ssum, o);
    float pc = ssum / 31.f;

    // ---- outputs (tuple flattened+concatenated as float32) ----
    const int OFF_FEAT = Bn * NGn * 3;
    const int OFF_SW   = OFF_FEAT + Bn * NGn * (FDn + 1);
    const int OFF_LAB  = OFF_SW + Bn * NGn;
    const int OFF_SIDX = OFF_LAB + Bn * NGn;
    if (lane < 3) out[s * 3 + lane] = coord[si * 3 + lane];
    out[OFF_FEAT + s * 33 + lane] = a_own;
    if (lane == 0) {
        out[OFF_FEAT + s * 33 + 32] = pc;
        out[OFF_SW + s]   = pc > 0.087266f ? 1.f : 0.f;
        out[OFF_LAB + s]  = (float)labels[si];
        out[OFF_SIDX + s] = (float)si;
    }
}

// ---------------------------------------------------------------------------
extern "C" void kernel_launch(void* const* d_in, const int* in_sizes, int n_in,
                              void* d_out, int out_size) {
    const float* coord  = (const float*)d_in[0];
    const float* feat   = (const float*)d_in[1];
    const int*   labels = (const int*)d_in[2];
    float* out = (float*)d_out;

    pack_kernel<<<(Bn * Nn / 4 + 255) / 256, 256>>>(coord);

    cudaError_t rc = cudaFuncSetAttribute(
        (const void*)fps_kernel16,
        cudaFuncAttributeNonPortableClusterSizeAllowed, 1);
    if (rc == cudaSuccess) {
        fps_kernel16<<<Bn * 16, 256>>>();
    } else {
        (void)cudaGetLastError();
        fps_kernel8<<<Bn * 8, 1024>>>();
    }

    knn_kernel<<<(Bn * NGn) / 16, 512>>>(coord, feat, labels, out);
}